// round 1
// baseline (speedup 1.0000x reference)
#include <cuda_runtime.h>
#include <math.h>

#define NE 8
#define TOPK 2
#define DIM 1024
#define IDIM 2048
#define NTOK 4096   // B*S = 4*1024

// ---------------- device scratch (static, allowed) ----------------
__device__ int   g_count[NE];
__device__ int   g_rows[NE * NTOK];    // token index per (expert, slot)
__device__ float g_w[NE * NTOK];       // routing weight per (expert, slot)
__device__ float g_h[(size_t)NE * NTOK * IDIM]; // 256 MB SwiGLU activations

// ---------------- init: zero counters + output ----------------
__global__ void init_kernel(float* __restrict__ out, int n) {
    int i = blockIdx.x * blockDim.x + threadIdx.x;
    if (i < NE) g_count[i] = 0;
    for (int j = i; j < n; j += gridDim.x * blockDim.x) out[j] = 0.0f;
}

// ---------------- routing: one warp per token ----------------
__global__ void route_kernel(const float* __restrict__ x,
                             const float* __restrict__ Wc,
                             const float* __restrict__ bc) {
    int gwarp = (blockIdx.x * blockDim.x + threadIdx.x) >> 5;
    int lane  = threadIdx.x & 31;
    if (gwarp >= NTOK) return;
    const float* xr = x + (size_t)gwarp * DIM;

    float acc[NE];
#pragma unroll
    for (int e = 0; e < NE; e++) acc[e] = 0.0f;

    for (int d = lane; d < DIM; d += 32) {
        float xv = xr[d];
#pragma unroll
        for (int e = 0; e < NE; e++) acc[e] += xv * Wc[e * DIM + d];
    }
#pragma unroll
    for (int e = 0; e < NE; e++) {
#pragma unroll
        for (int off = 16; off > 0; off >>= 1)
            acc[e] += __shfl_xor_sync(0xffffffffu, acc[e], off);
    }
    if (lane == 0) {
        float conf[NE];
#pragma unroll
        for (int e = 0; e < NE; e++)
            conf[e] = 1.0f / (1.0f + expf(-(acc[e] + bc[e])));
        // top-2, strict '>' keeps lowest index on ties (matches jax top_k)
        int i0 = 0;
#pragma unroll
        for (int e = 1; e < NE; e++) if (conf[e] > conf[i0]) i0 = e;
        int i1 = -1;
#pragma unroll
        for (int e = 0; e < NE; e++) {
            if (e == i0) continue;
            if (i1 < 0 || conf[e] > conf[i1]) i1 = e;
        }
        float v0 = conf[i0], v1 = conf[i1];
        // softmax over [v0, v1]
        float w0 = 1.0f / (1.0f + expf(v1 - v0));
        float w1 = 1.0f / (1.0f + expf(v0 - v1));
        int p0 = atomicAdd(&g_count[i0], 1);
        g_rows[i0 * NTOK + p0] = gwarp;
        g_w[i0 * NTOK + p0]    = w0;
        int p1 = atomicAdd(&g_count[i1], 1);
        g_rows[i1 * NTOK + p1] = gwarp;
        g_w[i1 * NTOK + p1]    = w1;
    }
}

// ---------------- up projection: h = silu(X Wg) * (X Wu) ----------------
// Tiles: TM=128 rows x TN=64 cols (of I), K-step 16. 256 threads, 8x4 microtile x2.
#define U_TM 128
#define U_TN 64
#define U_TK 16

__global__ __launch_bounds__(256, 2)
void up_kernel(const float* __restrict__ x,
               const float* __restrict__ Wg,
               const float* __restrict__ Wu) {
    int e  = blockIdx.z;
    int m0 = blockIdx.x * U_TM;
    int n0 = blockIdx.y * U_TN;
    int ne = g_count[e];
    if (m0 >= ne) return;

    __shared__ float As[U_TK][U_TM + 1];   // [k][m], padded
    __shared__ float Bg[U_TK][U_TN];
    __shared__ float Bu[U_TK][U_TN];
    __shared__ int   stok[U_TM];

    int tid = threadIdx.x;
    if (tid < U_TM) {
        int r = m0 + tid;
        stok[tid] = (r < ne) ? g_rows[e * NTOK + r] : -1;
    }
    __syncthreads();

    int ty = tid >> 4;        // 0..15 row group (8 rows each)
    int tx = tid & 15;        // 0..15 col group (4 cols each)

    const float* WgE = Wg + (size_t)e * DIM * IDIM;
    const float* WuE = Wu + (size_t)e * DIM * IDIM;

    float cg[8][4], cu[8][4];
#pragma unroll
    for (int i = 0; i < 8; i++)
#pragma unroll
        for (int j = 0; j < 4; j++) { cg[i][j] = 0.0f; cu[i][j] = 0.0f; }

    for (int k0 = 0; k0 < DIM; k0 += U_TK) {
        // A tile: 128 x 16 = 512 float4, gathered rows
#pragma unroll
        for (int it = 0; it < 2; it++) {
            int idx = tid + it * 256;          // 0..511
            int m   = idx >> 2;                // 0..127
            int kk4 = (idx & 3) * 4;
            float4 v = make_float4(0.f, 0.f, 0.f, 0.f);
            int tok = stok[m];
            if (tok >= 0)
                v = *reinterpret_cast<const float4*>(x + (size_t)tok * DIM + k0 + kk4);
            As[kk4 + 0][m] = v.x;
            As[kk4 + 1][m] = v.y;
            As[kk4 + 2][m] = v.z;
            As[kk4 + 3][m] = v.w;
        }
        // B tiles: 16 x 64 each = 256 float4
        {
            int kk = tid >> 4;                 // 0..15
            int j4 = (tid & 15) * 4;
            size_t off = (size_t)(k0 + kk) * IDIM + n0 + j4;
            *reinterpret_cast<float4*>(&Bg[kk][j4]) =
                *reinterpret_cast<const float4*>(WgE + off);
            *reinterpret_cast<float4*>(&Bu[kk][j4]) =
                *reinterpret_cast<const float4*>(WuE + off);
        }
        __syncthreads();

#pragma unroll
        for (int kk = 0; kk < U_TK; kk++) {
            float a[8], bg[4], bu[4];
#pragma unroll
            for (int i = 0; i < 8; i++) a[i] = As[kk][ty * 8 + i];
#pragma unroll
            for (int j = 0; j < 4; j++) { bg[j] = Bg[kk][tx * 4 + j]; bu[j] = Bu[kk][tx * 4 + j]; }
#pragma unroll
            for (int i = 0; i < 8; i++)
#pragma unroll
                for (int j = 0; j < 4; j++) {
                    cg[i][j] += a[i] * bg[j];
                    cu[i][j] += a[i] * bu[j];
                }
        }
        __syncthreads();
    }

    // epilogue: h = silu(g) * u
#pragma unroll
    for (int i = 0; i < 8; i++) {
        int r = m0 + ty * 8 + i;
        if (r >= ne) continue;
        float* hp = g_h + ((size_t)e * NTOK + r) * IDIM + n0 + tx * 4;
#pragma unroll
        for (int j = 0; j < 4; j++) {
            float g = cg[i][j];
            float u = cu[i][j];
            float s = g / (1.0f + expf(-g));
            hp[j] = s * u;
        }
    }
}

// ---------------- down projection + weighted combine ----------------
// Tiles: TM=128 x TN=128, K-step 16 over I=2048. 256 threads, 8x8 microtile.
#define D_TM 128
#define D_TN 128
#define D_TK 16

__global__ __launch_bounds__(256, 2)
void down_kernel(const float* __restrict__ Wd, float* __restrict__ out) {
    int e  = blockIdx.z;
    int m0 = blockIdx.x * D_TM;
    int n0 = blockIdx.y * D_TN;
    int ne = g_count[e];
    if (m0 >= ne) return;

    __shared__ float As[D_TK][D_TM + 1];
    __shared__ float Bs[D_TK][D_TN];

    int tid = threadIdx.x;
    int ty = tid >> 4;
    int tx = tid & 15;

    const float* WdE = Wd + (size_t)e * IDIM * DIM;
    const float* hE  = g_h + (size_t)e * NTOK * IDIM;

    float c[8][8];
#pragma unroll
    for (int i = 0; i < 8; i++)
#pragma unroll
        for (int j = 0; j < 8; j++) c[i][j] = 0.0f;

    for (int k0 = 0; k0 < IDIM; k0 += D_TK) {
        // A tile from h: 128 x 16 = 512 float4, rows contiguous per expert
#pragma unroll
        for (int it = 0; it < 2; it++) {
            int idx = tid + it * 256;
            int m   = idx >> 2;
            int kk4 = (idx & 3) * 4;
            float4 v = make_float4(0.f, 0.f, 0.f, 0.f);
            if (m0 + m < ne)
                v = *reinterpret_cast<const float4*>(hE + (size_t)(m0 + m) * IDIM + k0 + kk4);
            As[kk4 + 0][m] = v.x;
            As[kk4 + 1][m] = v.y;
            As[kk4 + 2][m] = v.z;
            As[kk4 + 3][m] = v.w;
        }
        // B tile: 16 x 128 = 512 float4
#pragma unroll
        for (int it = 0; it < 2; it++) {
            int idx = tid + it * 256;
            int kk  = idx >> 5;               // 0..15
            int j4  = (idx & 31) * 4;
            *reinterpret_cast<float4*>(&Bs[kk][j4]) =
                *reinterpret_cast<const float4*>(WdE + (size_t)(k0 + kk) * DIM + n0 + j4);
        }
        __syncthreads();

#pragma unroll
        for (int kk = 0; kk < D_TK; kk++) {
            float a[8], b[8];
#pragma unroll
            for (int i = 0; i < 8; i++) a[i] = As[kk][ty * 8 + i];
#pragma unroll
            for (int j = 0; j < 8; j++) b[j] = Bs[kk][tx * 8 + j];
#pragma unroll
            for (int i = 0; i < 8; i++)
#pragma unroll
                for (int j = 0; j < 8; j++) c[i][j] += a[i] * b[j];
        }
        __syncthreads();
    }

    // epilogue: out[token, :] += w * y   (2 fp32 atomics per element total)
#pragma unroll
    for (int i = 0; i < 8; i++) {
        int r = m0 + ty * 8 + i;
        if (r >= ne) continue;
        int   t = g_rows[e * NTOK + r];
        float w = g_w[e * NTOK + r];
        float* op = out + (size_t)t * DIM + n0 + tx * 8;
#pragma unroll
        for (int j = 0; j < 8; j++)
            atomicAdd(&op[j], w * c[i][j]);
    }
}

// ---------------- launcher ----------------
extern "C" void kernel_launch(void* const* d_in, const int* in_sizes, int n_in,
                              void* d_out, int out_size) {
    const float* hs = (const float*)d_in[0];  // [B,S,D]
    const float* Wc = (const float*)d_in[1];  // [E,D]
    const float* bc = (const float*)d_in[2];  // [E]
    const float* Wg = (const float*)d_in[3];  // [E,D,I]
    const float* Wu = (const float*)d_in[4];  // [E,D,I]
    const float* Wd = (const float*)d_in[5];  // [E,I,D]
    float* out = (float*)d_out;

    init_kernel<<<1024, 256>>>(out, out_size);

    // routing: 1 warp per token, 4096 warps -> 512 blocks * 8 warps
    route_kernel<<<(NTOK * 32) / 256, 256>>>(hs, Wc, bc);

    // up: grid (Mtiles, Ntiles, experts); blocks past count exit early
    dim3 gup(NTOK / U_TM, IDIM / U_TN, NE);   // (32, 32, 8)
    up_kernel<<<gup, 256>>>(hs, Wg, Wu);

    // down
    dim3 gdn(NTOK / D_TM, DIM / D_TN, NE);    // (32, 8, 8)
    down_kernel<<<gdn, 256>>>(Wd, out);
}

// round 3
// speedup vs baseline: 2.2768x; 2.2768x over previous
#include <cuda_runtime.h>
#include <cuda_bf16.h>
#include <math.h>
#include <stdint.h>

#define NE 8
#define DIM 1024
#define IDIM 2048
#define NTOK 4096
#define ESTRIDE 4096

// ---------------- device scratch ----------------
__device__ int   g_count[NE];
__device__ int   g_rows[NE * ESTRIDE];
__device__ float g_w[NE * ESTRIDE];
__device__ __nv_bfloat16 g_xh[NTOK * DIM];
__device__ __nv_bfloat16 g_xl[NTOK * DIM];
__device__ __nv_bfloat16 g_wg_h[NE * IDIM * DIM];   // [e][i][d] K-major (K=d)
__device__ __nv_bfloat16 g_wg_l[NE * IDIM * DIM];
__device__ __nv_bfloat16 g_wu_h[NE * IDIM * DIM];
__device__ __nv_bfloat16 g_wu_l[NE * IDIM * DIM];
__device__ __nv_bfloat16 g_wd_h[NE * DIM * IDIM];   // [e][d][i] K-major (K=i)
__device__ __nv_bfloat16 g_wd_l[NE * DIM * IDIM];
__device__ __nv_bfloat16 g_hh[(size_t)NE * ESTRIDE * IDIM];
__device__ __nv_bfloat16 g_hl[(size_t)NE * ESTRIDE * IDIM];

// ---------------- helpers ----------------
__device__ __forceinline__ uint32_t smem_u32(const void* p) {
    uint32_t a;
    asm("{ .reg .u64 t; cvta.to.shared.u64 t, %1; cvt.u32.u64 %0, t; }"
        : "=r"(a) : "l"(p));
    return a;
}

#define LDSM4(r0, r1, r2, r3, addr)                                          \
    asm volatile("ldmatrix.sync.aligned.m8n8.x4.shared.b16 {%0,%1,%2,%3}, [%4];" \
                 : "=r"(r0), "=r"(r1), "=r"(r2), "=r"(r3) : "r"(addr))

#define MMA16816(c, a, b)                                                    \
    asm volatile("mma.sync.aligned.m16n8k16.row.col.f32.bf16.bf16.f32 "      \
                 "{%0,%1,%2,%3},{%4,%5,%6,%7},{%8,%9},{%0,%1,%2,%3};"        \
                 : "+f"((c)[0]), "+f"((c)[1]), "+f"((c)[2]), "+f"((c)[3])    \
                 : "r"((a)[0]), "r"((a)[1]), "r"((a)[2]), "r"((a)[3]),       \
                   "r"((b)[0]), "r"((b)[1]))

// ---------------- init ----------------
__global__ void init_kernel(float* __restrict__ out, int n) {
    int i = blockIdx.x * blockDim.x + threadIdx.x;
    if (i < NE) g_count[i] = 0;
    for (int j = i; j < n; j += gridDim.x * blockDim.x) out[j] = 0.0f;
}

// ---------------- x -> bf16 hi/lo ----------------
__global__ void conv_x_kernel(const float* __restrict__ x) {
    int i = blockIdx.x * blockDim.x + threadIdx.x;
    const int N4 = NTOK * DIM / 4;
    for (int j = i; j < N4; j += gridDim.x * blockDim.x) {
        float4 v = reinterpret_cast<const float4*>(x)[j];
        __nv_bfloat16 h0 = __float2bfloat16(v.x), h1 = __float2bfloat16(v.y);
        __nv_bfloat16 h2 = __float2bfloat16(v.z), h3 = __float2bfloat16(v.w);
        __nv_bfloat16 hv[4] = {h0, h1, h2, h3};
        __nv_bfloat16 lv[4] = {
            __float2bfloat16(v.x - __bfloat162float(h0)),
            __float2bfloat16(v.y - __bfloat162float(h1)),
            __float2bfloat16(v.z - __bfloat162float(h2)),
            __float2bfloat16(v.w - __bfloat162float(h3))};
        reinterpret_cast<uint2*>(g_xh)[j] = *reinterpret_cast<uint2*>(hv);
        reinterpret_cast<uint2*>(g_xl)[j] = *reinterpret_cast<uint2*>(lv);
    }
}

// -------- transpose + split: in [E][R][C] fp32 -> out [E][C][R] bf16 hi/lo --------
__global__ void transpose_split_kernel(const float* __restrict__ in,
                                       __nv_bfloat16* __restrict__ oh,
                                       __nv_bfloat16* __restrict__ ol,
                                       int R, int C) {
    __shared__ float t[32][33];
    int e = blockIdx.z;
    const float* ine = in + (size_t)e * R * C;
    int c0 = blockIdx.x * 32, r0 = blockIdx.y * 32;
    int x = threadIdx.x, y = threadIdx.y;  // 32 x 8
#pragma unroll
    for (int i = 0; i < 32; i += 8)
        t[y + i][x] = ine[(size_t)(r0 + y + i) * C + c0 + x];
    __syncthreads();
    __nv_bfloat16* ohe = oh + (size_t)e * R * C;
    __nv_bfloat16* ole = ol + (size_t)e * R * C;
#pragma unroll
    for (int i = 0; i < 32; i += 8) {
        float v = t[x][y + i];
        __nv_bfloat16 h = __float2bfloat16(v);
        float lo = v - __bfloat162float(h);
        ohe[(size_t)(c0 + y + i) * R + r0 + x] = h;
        ole[(size_t)(c0 + y + i) * R + r0 + x] = __float2bfloat16(lo);
    }
}

// ---------------- routing: one warp per token ----------------
__global__ void route_kernel(const float* __restrict__ x,
                             const float* __restrict__ Wc,
                             const float* __restrict__ bc) {
    int gwarp = (blockIdx.x * blockDim.x + threadIdx.x) >> 5;
    int lane = threadIdx.x & 31;
    if (gwarp >= NTOK) return;
    const float* xr = x + (size_t)gwarp * DIM;
    float acc[NE];
#pragma unroll
    for (int e = 0; e < NE; e++) acc[e] = 0.0f;
    for (int d = lane; d < DIM; d += 32) {
        float xv = xr[d];
#pragma unroll
        for (int e = 0; e < NE; e++) acc[e] += xv * Wc[e * DIM + d];
    }
#pragma unroll
    for (int e = 0; e < NE; e++)
#pragma unroll
        for (int off = 16; off > 0; off >>= 1)
            acc[e] += __shfl_xor_sync(0xffffffffu, acc[e], off);
    if (lane == 0) {
        float conf[NE];
#pragma unroll
        for (int e = 0; e < NE; e++)
            conf[e] = 1.0f / (1.0f + expf(-(acc[e] + bc[e])));
        int i0 = 0;
#pragma unroll
        for (int e = 1; e < NE; e++) if (conf[e] > conf[i0]) i0 = e;
        int i1 = -1;
#pragma unroll
        for (int e = 0; e < NE; e++) {
            if (e == i0) continue;
            if (i1 < 0 || conf[e] > conf[i1]) i1 = e;
        }
        float v0 = conf[i0], v1 = conf[i1];
        float w0 = 1.0f / (1.0f + expf(v1 - v0));
        float w1 = 1.0f / (1.0f + expf(v0 - v1));
        int p0 = atomicAdd(&g_count[i0], 1);
        g_rows[i0 * ESTRIDE + p0] = gwarp;
        g_w[i0 * ESTRIDE + p0] = w0;
        int p1 = atomicAdd(&g_count[i1], 1);
        g_rows[i1 * ESTRIDE + p1] = gwarp;
        g_w[i1 * ESTRIDE + p1] = w1;
    }
}

// =======================================================================
// up: g = X*Wg^T, u = X*Wu^T (3-term bf16 split), h = silu(g)*u -> bf16 hi/lo
// CTA 128(M) x 64(N of IDIM), Kc=32; 8 warps (4x2), warp 32x32 per output
// =======================================================================
#define ASTRIDE 40   // halves per smem row (80B, conflict-free ldmatrix)

__global__ __launch_bounds__(256)
void up_mma_kernel() {
    __shared__ __align__(16) __nv_bfloat16 sAh[128 * ASTRIDE], sAl[128 * ASTRIDE];
    __shared__ __align__(16) __nv_bfloat16 sBgh[64 * ASTRIDE], sBgl[64 * ASTRIDE];
    __shared__ __align__(16) __nv_bfloat16 sBuh[64 * ASTRIDE], sBul[64 * ASTRIDE];
    __shared__ int stok[128];

    int e = blockIdx.z, m0 = blockIdx.x * 128, n0 = blockIdx.y * 64;
    int ne = g_count[e];
    if (m0 >= ne) return;
    int tid = threadIdx.x, wid = tid >> 5, l = tid & 31;
    if (tid < 128) stok[tid] = (m0 + tid < ne) ? g_rows[e * ESTRIDE + m0 + tid] : -1;
    __syncthreads();

    int wm = wid & 3, wn = wid >> 2;  // warp grid 4 x 2

    const __nv_bfloat16* WgH = g_wg_h + (size_t)e * IDIM * DIM;
    const __nv_bfloat16* WgL = g_wg_l + (size_t)e * IDIM * DIM;
    const __nv_bfloat16* WuH = g_wu_h + (size_t)e * IDIM * DIM;
    const __nv_bfloat16* WuL = g_wu_l + (size_t)e * IDIM * DIM;

    uint32_t aAh = smem_u32(sAh), aAl = smem_u32(sAl);
    uint32_t aBgh = smem_u32(sBgh), aBgl = smem_u32(sBgl);
    uint32_t aBuh = smem_u32(sBuh), aBul = smem_u32(sBul);

    // ldmatrix lane offsets
    int arow = (l & 7) + 8 * ((l >> 3) & 1);
    int acol = 8 * (l >> 4);
    int brow = (l & 7) + 8 * (l >> 4);
    int bcol = 8 * ((l >> 3) & 1);

    float cg[2][4][4], cu[2][4][4];
#pragma unroll
    for (int i = 0; i < 2; i++)
#pragma unroll
        for (int j = 0; j < 4; j++)
#pragma unroll
            for (int q = 0; q < 4; q++) { cg[i][j][q] = 0.f; cu[i][j][q] = 0.f; }

    for (int kc = 0; kc < DIM / 32; kc++) {
        int k0 = kc * 32;
        // A tile (gathered rows) hi+lo: 128 x 32 halves
#pragma unroll
        for (int it = 0; it < 2; it++) {
            int idx = tid + it * 256;
            int row = idx >> 2, ch = idx & 3;
            int tok = stok[row];
            uint4 vh = make_uint4(0, 0, 0, 0), vl = make_uint4(0, 0, 0, 0);
            if (tok >= 0) {
                size_t go = (size_t)tok * DIM + k0 + ch * 8;
                vh = *reinterpret_cast<const uint4*>(g_xh + go);
                vl = *reinterpret_cast<const uint4*>(g_xl + go);
            }
            int so = row * ASTRIDE + ch * 8;
            *reinterpret_cast<uint4*>(sAh + so) = vh;
            *reinterpret_cast<uint4*>(sAl + so) = vl;
        }
        // B tiles: 64 x 32 halves each
        {
            int row = tid >> 2, ch = tid & 3;
            size_t go = (size_t)(n0 + row) * DIM + k0 + ch * 8;
            int so = row * ASTRIDE + ch * 8;
            *reinterpret_cast<uint4*>(sBgh + so) = *reinterpret_cast<const uint4*>(WgH + go);
            *reinterpret_cast<uint4*>(sBgl + so) = *reinterpret_cast<const uint4*>(WgL + go);
            *reinterpret_cast<uint4*>(sBuh + so) = *reinterpret_cast<const uint4*>(WuH + go);
            *reinterpret_cast<uint4*>(sBul + so) = *reinterpret_cast<const uint4*>(WuL + go);
        }
        __syncthreads();

#pragma unroll
        for (int ks = 0; ks < 2; ks++) {
            int kk = ks * 16;
            uint32_t ah[2][4], al[2][4];
#pragma unroll
            for (int mf = 0; mf < 2; mf++) {
                uint32_t off = (uint32_t)(((wm * 32 + mf * 16 + arow) * ASTRIDE + kk + acol) * 2);
                LDSM4(ah[mf][0], ah[mf][1], ah[mf][2], ah[mf][3], aAh + off);
                LDSM4(al[mf][0], al[mf][1], al[mf][2], al[mf][3], aAl + off);
            }
            uint32_t bgh[4][2], bgl[4][2], buh[4][2], bul[4][2];
#pragma unroll
            for (int p = 0; p < 2; p++) {
                uint32_t off = (uint32_t)(((wn * 32 + p * 16 + brow) * ASTRIDE + kk + bcol) * 2);
                LDSM4(bgh[2 * p][0], bgh[2 * p][1], bgh[2 * p + 1][0], bgh[2 * p + 1][1], aBgh + off);
                LDSM4(bgl[2 * p][0], bgl[2 * p][1], bgl[2 * p + 1][0], bgl[2 * p + 1][1], aBgl + off);
                LDSM4(buh[2 * p][0], buh[2 * p][1], buh[2 * p + 1][0], buh[2 * p + 1][1], aBuh + off);
                LDSM4(bul[2 * p][0], bul[2 * p][1], bul[2 * p + 1][0], bul[2 * p + 1][1], aBul + off);
            }
#pragma unroll
            for (int mf = 0; mf < 2; mf++)
#pragma unroll
                for (int nf = 0; nf < 4; nf++) {
                    MMA16816(cg[mf][nf], ah[mf], bgh[nf]);
                    MMA16816(cg[mf][nf], ah[mf], bgl[nf]);
                    MMA16816(cg[mf][nf], al[mf], bgh[nf]);
                    MMA16816(cu[mf][nf], ah[mf], buh[nf]);
                    MMA16816(cu[mf][nf], ah[mf], bul[nf]);
                    MMA16816(cu[mf][nf], al[mf], buh[nf]);
                }
        }
        __syncthreads();
    }

    // epilogue: h = silu(g) * u, split to bf16 hi/lo
    __nv_bfloat16* hh = g_hh + (size_t)e * ESTRIDE * IDIM;
    __nv_bfloat16* hl = g_hl + (size_t)e * ESTRIDE * IDIM;
#pragma unroll
    for (int mf = 0; mf < 2; mf++) {
        int r_lo = m0 + wm * 32 + mf * 16 + (l >> 2);
        int r_hi = r_lo + 8;
#pragma unroll
        for (int nf = 0; nf < 4; nf++) {
            int col = n0 + wn * 32 + nf * 8 + 2 * (l & 3);
#pragma unroll
            for (int half = 0; half < 2; half++) {
                int r = half ? r_hi : r_lo;
                if (r >= ne) continue;
                float gv0 = cg[mf][nf][half * 2 + 0], gv1 = cg[mf][nf][half * 2 + 1];
                float uv0 = cu[mf][nf][half * 2 + 0], uv1 = cu[mf][nf][half * 2 + 1];
                float h0 = uv0 * gv0 / (1.0f + expf(-gv0));
                float h1 = uv1 * gv1 / (1.0f + expf(-gv1));
                __nv_bfloat16 b0 = __float2bfloat16(h0), b1 = __float2bfloat16(h1);
                __nv_bfloat16 l0 = __float2bfloat16(h0 - __bfloat162float(b0));
                __nv_bfloat16 l1 = __float2bfloat16(h1 - __bfloat162float(b1));
                __nv_bfloat16 ph[2] = {b0, b1}, pl[2] = {l0, l1};
                size_t off = (size_t)r * IDIM + col;
                *reinterpret_cast<uint32_t*>(hh + off) = *reinterpret_cast<uint32_t*>(ph);
                *reinterpret_cast<uint32_t*>(hl + off) = *reinterpret_cast<uint32_t*>(pl);
            }
        }
    }
}

// =======================================================================
// down: Y = H*Wd^T; out[token] += w * Y
// CTA 128(M) x 128(N of DIM), Kc=32 over K=2048; warp 32x64
// =======================================================================
__global__ __launch_bounds__(256)
void down_mma_kernel(float* __restrict__ out) {
    __shared__ __align__(16) __nv_bfloat16 sAh[128 * ASTRIDE], sAl[128 * ASTRIDE];
    __shared__ __align__(16) __nv_bfloat16 sBh[128 * ASTRIDE], sBl[128 * ASTRIDE];

    int e = blockIdx.z, m0 = blockIdx.x * 128, n0 = blockIdx.y * 128;
    int ne = g_count[e];
    if (m0 >= ne) return;
    int tid = threadIdx.x, wid = tid >> 5, l = tid & 31;
    int wm = wid & 3, wn = wid >> 2;

    const __nv_bfloat16* AH = g_hh + (size_t)e * ESTRIDE * IDIM;
    const __nv_bfloat16* AL = g_hl + (size_t)e * ESTRIDE * IDIM;
    const __nv_bfloat16* BH = g_wd_h + (size_t)e * DIM * IDIM;
    const __nv_bfloat16* BL = g_wd_l + (size_t)e * DIM * IDIM;

    uint32_t aAh = smem_u32(sAh), aAl = smem_u32(sAl);
    uint32_t aBh = smem_u32(sBh), aBl = smem_u32(sBl);

    int arow = (l & 7) + 8 * ((l >> 3) & 1);
    int acol = 8 * (l >> 4);
    int brow = (l & 7) + 8 * (l >> 4);
    int bcol = 8 * ((l >> 3) & 1);

    float c[2][8][4];
#pragma unroll
    for (int i = 0; i < 2; i++)
#pragma unroll
        for (int j = 0; j < 8; j++)
#pragma unroll
            for (int q = 0; q < 4; q++) c[i][j][q] = 0.f;

    for (int kc = 0; kc < IDIM / 32; kc++) {
        int k0 = kc * 32;
#pragma unroll
        for (int it = 0; it < 2; it++) {
            int idx = tid + it * 256;
            int row = idx >> 2, ch = idx & 3;
            size_t ga = (size_t)(m0 + row) * IDIM + k0 + ch * 8;
            size_t gb = (size_t)(n0 + row) * IDIM + k0 + ch * 8;
            int so = row * ASTRIDE + ch * 8;
            *reinterpret_cast<uint4*>(sAh + so) = *reinterpret_cast<const uint4*>(AH + ga);
            *reinterpret_cast<uint4*>(sAl + so) = *reinterpret_cast<const uint4*>(AL + ga);
            *reinterpret_cast<uint4*>(sBh + so) = *reinterpret_cast<const uint4*>(BH + gb);
            *reinterpret_cast<uint4*>(sBl + so) = *reinterpret_cast<const uint4*>(BL + gb);
        }
        __syncthreads();

#pragma unroll
        for (int ks = 0; ks < 2; ks++) {
            int kk = ks * 16;
            uint32_t ah[2][4], al[2][4];
#pragma unroll
            for (int mf = 0; mf < 2; mf++) {
                uint32_t off = (uint32_t)(((wm * 32 + mf * 16 + arow) * ASTRIDE + kk + acol) * 2);
                LDSM4(ah[mf][0], ah[mf][1], ah[mf][2], ah[mf][3], aAh + off);
                LDSM4(al[mf][0], al[mf][1], al[mf][2], al[mf][3], aAl + off);
            }
            uint32_t bh[8][2], bl[8][2];
#pragma unroll
            for (int p = 0; p < 4; p++) {
                uint32_t off = (uint32_t)(((wn * 64 + p * 16 + brow) * ASTRIDE + kk + bcol) * 2);
                LDSM4(bh[2 * p][0], bh[2 * p][1], bh[2 * p + 1][0], bh[2 * p + 1][1], aBh + off);
                LDSM4(bl[2 * p][0], bl[2 * p][1], bl[2 * p + 1][0], bl[2 * p + 1][1], aBl + off);
            }
#pragma unroll
            for (int mf = 0; mf < 2; mf++)
#pragma unroll
                for (int nf = 0; nf < 8; nf++) {
                    MMA16816(c[mf][nf], ah[mf], bh[nf]);
                    MMA16816(c[mf][nf], ah[mf], bl[nf]);
                    MMA16816(c[mf][nf], al[mf], bh[nf]);
                }
        }
        __syncthreads();
    }

    // epilogue: weighted atomic combine
#pragma unroll
    for (int mf = 0; mf < 2; mf++) {
        int r_lo = m0 + wm * 32 + mf * 16 + (l >> 2);
#pragma unroll
        for (int half = 0; half < 2; half++) {
            int r = r_lo + half * 8;
            if (r >= ne) continue;
            int   t = g_rows[e * ESTRIDE + r];
            float w = g_w[e * ESTRIDE + r];
            float* op = out + (size_t)t * DIM;
#pragma unroll
            for (int nf = 0; nf < 8; nf++) {
                int col = n0 + wn * 64 + nf * 8 + 2 * (l & 3);
                atomicAdd(op + col,     w * c[mf][nf][half * 2 + 0]);
                atomicAdd(op + col + 1, w * c[mf][nf][half * 2 + 1]);
            }
        }
    }
}

// ---------------- launcher ----------------
extern "C" void kernel_launch(void* const* d_in, const int* in_sizes, int n_in,
                              void* d_out, int out_size) {
    const float* hs = (const float*)d_in[0];
    const float* Wc = (const float*)d_in[1];
    const float* bc = (const float*)d_in[2];
    const float* Wg = (const float*)d_in[3];
    const float* Wu = (const float*)d_in[4];
    const float* Wd = (const float*)d_in[5];
    float* out = (float*)d_out;

    init_kernel<<<1024, 256>>>(out, out_size);
    conv_x_kernel<<<2048, 256>>>(hs);

    __nv_bfloat16 *wg_h, *wg_l, *wu_h, *wu_l, *wd_h, *wd_l;
    cudaGetSymbolAddress((void**)&wg_h, g_wg_h);
    cudaGetSymbolAddress((void**)&wg_l, g_wg_l);
    cudaGetSymbolAddress((void**)&wu_h, g_wu_h);
    cudaGetSymbolAddress((void**)&wu_l, g_wu_l);
    cudaGetSymbolAddress((void**)&wd_h, g_wd_h);
    cudaGetSymbolAddress((void**)&wd_l, g_wd_l);

    dim3 tb(32, 8);
    transpose_split_kernel<<<dim3(IDIM / 32, DIM / 32, NE), tb>>>(Wg, wg_h, wg_l, DIM, IDIM);
    transpose_split_kernel<<<dim3(IDIM / 32, DIM / 32, NE), tb>>>(Wu, wu_h, wu_l, DIM, IDIM);
    transpose_split_kernel<<<dim3(DIM / 32, IDIM / 32, NE), tb>>>(Wd, wd_h, wd_l, IDIM, DIM);

    route_kernel<<<(NTOK * 32) / 256, 256>>>(hs, Wc, bc);

    up_mma_kernel<<<dim3(NTOK / 128, IDIM / 64, NE), 256>>>();
    down_mma_kernel<<<dim3(NTOK / 128, DIM / 128, NE), 256>>>(out);
}

// round 4
// speedup vs baseline: 2.3695x; 1.0407x over previous
#include <cuda_runtime.h>
#include <cuda_bf16.h>
#include <math.h>
#include <stdint.h>

#define NE 8
#define DIM 1024
#define IDIM 2048
#define NTOK 4096
#define ESTRIDE 4096

// ---------------- device scratch ----------------
__device__ int   g_count[NE];
__device__ int   g_rows[NE * ESTRIDE];
__device__ float g_w[NE * ESTRIDE];
__device__ __nv_bfloat16 g_xh[NTOK * DIM];
__device__ __nv_bfloat16 g_xl[NTOK * DIM];
__device__ __nv_bfloat16 g_wg_h[NE * IDIM * DIM];   // [e][i][d] K-major (K=d)
__device__ __nv_bfloat16 g_wg_l[NE * IDIM * DIM];
__device__ __nv_bfloat16 g_wu_h[NE * IDIM * DIM];
__device__ __nv_bfloat16 g_wu_l[NE * IDIM * DIM];
__device__ __nv_bfloat16 g_wd_h[NE * DIM * IDIM];   // [e][d][i] K-major (K=i)
__device__ __nv_bfloat16 g_wd_l[NE * DIM * IDIM];
__device__ __nv_bfloat16 g_hh[(size_t)NE * ESTRIDE * IDIM];
__device__ __nv_bfloat16 g_hl[(size_t)NE * ESTRIDE * IDIM];

// ---------------- helpers ----------------
__device__ __forceinline__ uint32_t smem_u32(const void* p) {
    uint32_t a;
    asm("{ .reg .u64 t; cvta.to.shared.u64 t, %1; cvt.u32.u64 %0, t; }"
        : "=r"(a) : "l"(p));
    return a;
}

#define LDSM4(r0, r1, r2, r3, addr)                                          \
    asm volatile("ldmatrix.sync.aligned.m8n8.x4.shared.b16 {%0,%1,%2,%3}, [%4];" \
                 : "=r"(r0), "=r"(r1), "=r"(r2), "=r"(r3) : "r"(addr))

#define MMA16816(c, a, b)                                                    \
    asm volatile("mma.sync.aligned.m16n8k16.row.col.f32.bf16.bf16.f32 "      \
                 "{%0,%1,%2,%3},{%4,%5,%6,%7},{%8,%9},{%0,%1,%2,%3};"        \
                 : "+f"((c)[0]), "+f"((c)[1]), "+f"((c)[2]), "+f"((c)[3])    \
                 : "r"((a)[0]), "r"((a)[1]), "r"((a)[2]), "r"((a)[3]),       \
                   "r"((b)[0]), "r"((b)[1]))

#define CPA16(dst, src, sz)                                                  \
    asm volatile("cp.async.cg.shared.global [%0], [%1], 16, %2;"             \
                 :: "r"(dst), "l"(src), "r"(sz) : "memory")
#define CP_COMMIT() asm volatile("cp.async.commit_group;" ::: "memory")
#define CP_WAIT(n)  asm volatile("cp.async.wait_group %0;" ::"n"(n) : "memory")

// ---------------- init ----------------
__global__ void init_kernel(float* __restrict__ out, int n) {
    int i = blockIdx.x * blockDim.x + threadIdx.x;
    if (i < NE) g_count[i] = 0;
    for (int j = i; j < n; j += gridDim.x * blockDim.x) out[j] = 0.0f;
}

// ---------------- x -> bf16 hi/lo ----------------
__global__ void conv_x_kernel(const float* __restrict__ x) {
    int i = blockIdx.x * blockDim.x + threadIdx.x;
    const int N4 = NTOK * DIM / 4;
    for (int j = i; j < N4; j += gridDim.x * blockDim.x) {
        float4 v = reinterpret_cast<const float4*>(x)[j];
        __nv_bfloat16 h0 = __float2bfloat16(v.x), h1 = __float2bfloat16(v.y);
        __nv_bfloat16 h2 = __float2bfloat16(v.z), h3 = __float2bfloat16(v.w);
        __nv_bfloat16 hv[4] = {h0, h1, h2, h3};
        __nv_bfloat16 lv[4] = {
            __float2bfloat16(v.x - __bfloat162float(h0)),
            __float2bfloat16(v.y - __bfloat162float(h1)),
            __float2bfloat16(v.z - __bfloat162float(h2)),
            __float2bfloat16(v.w - __bfloat162float(h3))};
        reinterpret_cast<uint2*>(g_xh)[j] = *reinterpret_cast<uint2*>(hv);
        reinterpret_cast<uint2*>(g_xl)[j] = *reinterpret_cast<uint2*>(lv);
    }
}

// -------- transpose + split: in [E][R][C] fp32 -> out [E][C][R] bf16 hi/lo --------
__global__ void transpose_split_kernel(const float* __restrict__ in,
                                       __nv_bfloat16* __restrict__ oh,
                                       __nv_bfloat16* __restrict__ ol,
                                       int R, int C) {
    __shared__ float t[32][33];
    int e = blockIdx.z;
    const float* ine = in + (size_t)e * R * C;
    int c0 = blockIdx.x * 32, r0 = blockIdx.y * 32;
    int x = threadIdx.x, y = threadIdx.y;  // 32 x 8
#pragma unroll
    for (int i = 0; i < 32; i += 8)
        t[y + i][x] = ine[(size_t)(r0 + y + i) * C + c0 + x];
    __syncthreads();
    __nv_bfloat16* ohe = oh + (size_t)e * R * C;
    __nv_bfloat16* ole = ol + (size_t)e * R * C;
#pragma unroll
    for (int i = 0; i < 32; i += 8) {
        float v = t[x][y + i];
        __nv_bfloat16 h = __float2bfloat16(v);
        float lo = v - __bfloat162float(h);
        ohe[(size_t)(c0 + y + i) * R + r0 + x] = h;
        ole[(size_t)(c0 + y + i) * R + r0 + x] = __float2bfloat16(lo);
    }
}

// ---------------- routing: one warp per token ----------------
__global__ void route_kernel(const float* __restrict__ x,
                             const float* __restrict__ Wc,
                             const float* __restrict__ bc) {
    int gwarp = (blockIdx.x * blockDim.x + threadIdx.x) >> 5;
    int lane = threadIdx.x & 31;
    if (gwarp >= NTOK) return;
    const float* xr = x + (size_t)gwarp * DIM;
    float acc[NE];
#pragma unroll
    for (int e = 0; e < NE; e++) acc[e] = 0.0f;
    for (int d = lane; d < DIM; d += 32) {
        float xv = xr[d];
#pragma unroll
        for (int e = 0; e < NE; e++) acc[e] += xv * Wc[e * DIM + d];
    }
#pragma unroll
    for (int e = 0; e < NE; e++)
#pragma unroll
        for (int off = 16; off > 0; off >>= 1)
            acc[e] += __shfl_xor_sync(0xffffffffu, acc[e], off);
    if (lane == 0) {
        float conf[NE];
#pragma unroll
        for (int e = 0; e < NE; e++)
            conf[e] = 1.0f / (1.0f + expf(-(acc[e] + bc[e])));
        int i0 = 0;
#pragma unroll
        for (int e = 1; e < NE; e++) if (conf[e] > conf[i0]) i0 = e;
        int i1 = -1;
#pragma unroll
        for (int e = 0; e < NE; e++) {
            if (e == i0) continue;
            if (i1 < 0 || conf[e] > conf[i1]) i1 = e;
        }
        float v0 = conf[i0], v1 = conf[i1];
        float w0 = 1.0f / (1.0f + expf(v1 - v0));
        float w1 = 1.0f / (1.0f + expf(v0 - v1));
        int p0 = atomicAdd(&g_count[i0], 1);
        g_rows[i0 * ESTRIDE + p0] = gwarp;
        g_w[i0 * ESTRIDE + p0] = w0;
        int p1 = atomicAdd(&g_count[i1], 1);
        g_rows[i1 * ESTRIDE + p1] = gwarp;
        g_w[i1 * ESTRIDE + p1] = w1;
    }
}

// =======================================================================
// Tiling constants. smem rows are 80B (40 halves) for conflict-free ldmatrix.
// =======================================================================
#define ASTRIDE 40          // halves per smem row
#define RBYTES  80          // bytes per smem row

// -------- up kernel smem stage layout (bytes) --------
#define U_AH  0
#define U_AL  10240         // 128*80
#define U_BGH 20480
#define U_BGL 25600         // +64*80
#define U_BUH 30720
#define U_BUL 35840
#define U_STAGE 40960
#define U_SMEM (2 * U_STAGE)

// -------- down kernel smem stage layout --------
#define D_AH  0
#define D_AL  10240
#define D_BH  20480
#define D_BL  30720
#define D_STAGE 40960
#define D_SMEM (2 * D_STAGE)

// =======================================================================
// up: g = X*Wg^T, u = X*Wu^T (3-term bf16 split), h = silu(g)*u -> bf16 hi/lo
// CTA 128(M) x 64(N of IDIM), Kc=32; cp.async depth-2 pipeline
// =======================================================================
__global__ __launch_bounds__(256)
void up_mma_kernel() {
    extern __shared__ char dsm[];
    __shared__ int stok[128];

    int e = blockIdx.z, m0 = blockIdx.x * 128, n0 = blockIdx.y * 64;
    int ne = g_count[e];
    if (m0 >= ne) return;
    int tid = threadIdx.x, wid = tid >> 5, l = tid & 31;
    if (tid < 128) stok[tid] = (m0 + tid < ne) ? g_rows[e * ESTRIDE + m0 + tid] : -1;
    __syncthreads();

    int wm = wid & 3, wn = wid >> 2;

    const __nv_bfloat16* WgH = g_wg_h + (size_t)e * IDIM * DIM;
    const __nv_bfloat16* WgL = g_wg_l + (size_t)e * IDIM * DIM;
    const __nv_bfloat16* WuH = g_wu_h + (size_t)e * IDIM * DIM;
    const __nv_bfloat16* WuL = g_wu_l + (size_t)e * IDIM * DIM;

    uint32_t sb = smem_u32(dsm);

    // per-thread load coordinates
    int arow0 = tid >> 2, ach = tid & 3;              // A: rows tid>>2 and +64
    int brow = tid >> 2, bch = tid & 3;               // B: 64 rows x 4 chunks

    // ldmatrix lane offsets
    int lar = (l & 7) + 8 * ((l >> 3) & 1);
    int lac = 8 * (l >> 4);
    int lbr = (l & 7) + 8 * (l >> 4);
    int lbc = 8 * ((l >> 3) & 1);

    float cg[2][4][4], cu[2][4][4];
#pragma unroll
    for (int i = 0; i < 2; i++)
#pragma unroll
        for (int j = 0; j < 4; j++)
#pragma unroll
            for (int q = 0; q < 4; q++) { cg[i][j][q] = 0.f; cu[i][j][q] = 0.f; }

    const int NK = DIM / 32;

    auto load_stage = [&](int kc, int s) {
        uint32_t st = sb + s * U_STAGE;
        int k0 = kc * 32;
        // A hi/lo: rows arow0 and arow0+64
#pragma unroll
        for (int it = 0; it < 2; it++) {
            int row = arow0 + it * 64;
            int tok = stok[row];
            uint32_t sz = (tok >= 0) ? 16u : 0u;
            const __nv_bfloat16* srch = g_xh;
            const __nv_bfloat16* srcl = g_xl;
            size_t go = (tok >= 0) ? ((size_t)tok * DIM + k0 + ach * 8) : 0;
            uint32_t so = row * RBYTES + ach * 16;
            CPA16(st + U_AH + so, srch + go, sz);
            CPA16(st + U_AL + so, srcl + go, sz);
        }
        // B tiles
        {
            size_t go = (size_t)(n0 + brow) * DIM + k0 + bch * 8;
            uint32_t so = brow * RBYTES + bch * 16;
            CPA16(st + U_BGH + so, WgH + go, 16u);
            CPA16(st + U_BGL + so, WgL + go, 16u);
            CPA16(st + U_BUH + so, WuH + go, 16u);
            CPA16(st + U_BUL + so, WuL + go, 16u);
        }
        CP_COMMIT();
    };

    load_stage(0, 0);

    for (int kc = 0; kc < NK; kc++) {
        if (kc + 1 < NK) load_stage(kc + 1, (kc + 1) & 1);
        if (kc + 1 < NK) { CP_WAIT(1); } else { CP_WAIT(0); }
        __syncthreads();

        uint32_t st = sb + (kc & 1) * U_STAGE;
#pragma unroll
        for (int ks = 0; ks < 2; ks++) {
            int kkb = ks * 32;  // 16 halves = 32 bytes
            uint32_t ah[2][4], al[2][4];
#pragma unroll
            for (int mf = 0; mf < 2; mf++) {
                uint32_t off = (uint32_t)((wm * 32 + mf * 16 + lar) * RBYTES + kkb + lac * 2);
                LDSM4(ah[mf][0], ah[mf][1], ah[mf][2], ah[mf][3], st + U_AH + off);
                LDSM4(al[mf][0], al[mf][1], al[mf][2], al[mf][3], st + U_AL + off);
            }
#pragma unroll
            for (int p = 0; p < 2; p++) {
                uint32_t off = (uint32_t)((wn * 32 + p * 16 + lbr) * RBYTES + kkb + lbc * 2);
                uint32_t bgh[2][2], bgl[2][2], buh[2][2], bul[2][2];
                LDSM4(bgh[0][0], bgh[0][1], bgh[1][0], bgh[1][1], st + U_BGH + off);
                LDSM4(bgl[0][0], bgl[0][1], bgl[1][0], bgl[1][1], st + U_BGL + off);
                LDSM4(buh[0][0], buh[0][1], buh[1][0], buh[1][1], st + U_BUH + off);
                LDSM4(bul[0][0], bul[0][1], bul[1][0], bul[1][1], st + U_BUL + off);
#pragma unroll
                for (int mf = 0; mf < 2; mf++)
#pragma unroll
                    for (int q = 0; q < 2; q++) {
                        int nf = 2 * p + q;
                        MMA16816(cg[mf][nf], ah[mf], bgh[q]);
                        MMA16816(cg[mf][nf], ah[mf], bgl[q]);
                        MMA16816(cg[mf][nf], al[mf], bgh[q]);
                        MMA16816(cu[mf][nf], ah[mf], buh[q]);
                        MMA16816(cu[mf][nf], ah[mf], bul[q]);
                        MMA16816(cu[mf][nf], al[mf], buh[q]);
                    }
            }
        }
        __syncthreads();
    }

    // epilogue: h = silu(g) * u, split to bf16 hi/lo
    __nv_bfloat16* hh = g_hh + (size_t)e * ESTRIDE * IDIM;
    __nv_bfloat16* hl = g_hl + (size_t)e * ESTRIDE * IDIM;
#pragma unroll
    for (int mf = 0; mf < 2; mf++) {
        int r_lo = m0 + wm * 32 + mf * 16 + (l >> 2);
#pragma unroll
        for (int nf = 0; nf < 4; nf++) {
            int col = n0 + wn * 32 + nf * 8 + 2 * (l & 3);
#pragma unroll
            for (int half = 0; half < 2; half++) {
                int r = r_lo + half * 8;
                if (r >= ne) continue;
                float gv0 = cg[mf][nf][half * 2 + 0], gv1 = cg[mf][nf][half * 2 + 1];
                float uv0 = cu[mf][nf][half * 2 + 0], uv1 = cu[mf][nf][half * 2 + 1];
                float h0 = uv0 * gv0 / (1.0f + expf(-gv0));
                float h1 = uv1 * gv1 / (1.0f + expf(-gv1));
                __nv_bfloat16 b0 = __float2bfloat16(h0), b1 = __float2bfloat16(h1);
                __nv_bfloat16 l0 = __float2bfloat16(h0 - __bfloat162float(b0));
                __nv_bfloat16 l1 = __float2bfloat16(h1 - __bfloat162float(b1));
                __nv_bfloat16 ph[2] = {b0, b1}, pl[2] = {l0, l1};
                size_t off = (size_t)r * IDIM + col;
                *reinterpret_cast<uint32_t*>(hh + off) = *reinterpret_cast<uint32_t*>(ph);
                *reinterpret_cast<uint32_t*>(hl + off) = *reinterpret_cast<uint32_t*>(pl);
            }
        }
    }
}

// =======================================================================
// down: Y = H*Wd^T; out[token] += w * Y
// CTA 128(M) x 128(N of DIM), Kc=32 over K=2048; cp.async depth-2
// =======================================================================
__global__ __launch_bounds__(256)
void down_mma_kernel(float* __restrict__ out) {
    extern __shared__ char dsm[];

    int e = blockIdx.z, m0 = blockIdx.x * 128, n0 = blockIdx.y * 128;
    int ne = g_count[e];
    if (m0 >= ne) return;
    int tid = threadIdx.x, wid = tid >> 5, l = tid & 31;
    int wm = wid & 3, wn = wid >> 2;

    const __nv_bfloat16* AH = g_hh + (size_t)e * ESTRIDE * IDIM;
    const __nv_bfloat16* AL = g_hl + (size_t)e * ESTRIDE * IDIM;
    const __nv_bfloat16* BH = g_wd_h + (size_t)e * DIM * IDIM;
    const __nv_bfloat16* BL = g_wd_l + (size_t)e * DIM * IDIM;

    uint32_t sb = smem_u32(dsm);

    int row0 = tid >> 2, ch = tid & 3;

    int lar = (l & 7) + 8 * ((l >> 3) & 1);
    int lac = 8 * (l >> 4);
    int lbr = (l & 7) + 8 * (l >> 4);
    int lbc = 8 * ((l >> 3) & 1);

    float c[2][8][4];
#pragma unroll
    for (int i = 0; i < 2; i++)
#pragma unroll
        for (int j = 0; j < 8; j++)
#pragma unroll
            for (int q = 0; q < 4; q++) c[i][j][q] = 0.f;

    const int NK = IDIM / 32;

    auto load_stage = [&](int kc, int s) {
        uint32_t st = sb + s * D_STAGE;
        int k0 = kc * 32;
#pragma unroll
        for (int it = 0; it < 2; it++) {
            int row = row0 + it * 64;
            uint32_t so = row * RBYTES + ch * 16;
            // A: zero-fill rows past ne (g_hh stale there)
            uint32_t sz = (m0 + row < ne) ? 16u : 0u;
            size_t ga = (m0 + row < ne) ? ((size_t)(m0 + row) * IDIM + k0 + ch * 8) : 0;
            CPA16(st + D_AH + so, AH + ga, sz);
            CPA16(st + D_AL + so, AL + ga, sz);
            size_t gb = (size_t)(n0 + row) * IDIM + k0 + ch * 8;
            CPA16(st + D_BH + so, BH + gb, 16u);
            CPA16(st + D_BL + so, BL + gb, 16u);
        }
        CP_COMMIT();
    };

    load_stage(0, 0);

    for (int kc = 0; kc < NK; kc++) {
        if (kc + 1 < NK) load_stage(kc + 1, (kc + 1) & 1);
        if (kc + 1 < NK) { CP_WAIT(1); } else { CP_WAIT(0); }
        __syncthreads();

        uint32_t st = sb + (kc & 1) * D_STAGE;
#pragma unroll
        for (int ks = 0; ks < 2; ks++) {
            int kkb = ks * 32;
            uint32_t ah[2][4], al[2][4];
#pragma unroll
            for (int mf = 0; mf < 2; mf++) {
                uint32_t off = (uint32_t)((wm * 32 + mf * 16 + lar) * RBYTES + kkb + lac * 2);
                LDSM4(ah[mf][0], ah[mf][1], ah[mf][2], ah[mf][3], st + D_AH + off);
                LDSM4(al[mf][0], al[mf][1], al[mf][2], al[mf][3], st + D_AL + off);
            }
#pragma unroll
            for (int p = 0; p < 4; p++) {
                uint32_t off = (uint32_t)((wn * 64 + p * 16 + lbr) * RBYTES + kkb + lbc * 2);
                uint32_t bh[2][2], bl[2][2];
                LDSM4(bh[0][0], bh[0][1], bh[1][0], bh[1][1], st + D_BH + off);
                LDSM4(bl[0][0], bl[0][1], bl[1][0], bl[1][1], st + D_BL + off);
#pragma unroll
                for (int mf = 0; mf < 2; mf++)
#pragma unroll
                    for (int q = 0; q < 2; q++) {
                        int nf = 2 * p + q;
                        MMA16816(c[mf][nf], ah[mf], bh[q]);
                        MMA16816(c[mf][nf], ah[mf], bl[q]);
                        MMA16816(c[mf][nf], al[mf], bh[q]);
                    }
            }
        }
        __syncthreads();
    }

    // epilogue: weighted atomic combine
#pragma unroll
    for (int mf = 0; mf < 2; mf++) {
        int r_lo = m0 + wm * 32 + mf * 16 + (l >> 2);
#pragma unroll
        for (int half = 0; half < 2; half++) {
            int r = r_lo + half * 8;
            if (r >= ne) continue;
            int   t = g_rows[e * ESTRIDE + r];
            float w = g_w[e * ESTRIDE + r];
            float* op = out + (size_t)t * DIM;
#pragma unroll
            for (int nf = 0; nf < 8; nf++) {
                int col = n0 + wn * 64 + nf * 8 + 2 * (l & 3);
                atomicAdd(op + col,     w * c[mf][nf][half * 2 + 0]);
                atomicAdd(op + col + 1, w * c[mf][nf][half * 2 + 1]);
            }
        }
    }
}

// ---------------- launcher ----------------
extern "C" void kernel_launch(void* const* d_in, const int* in_sizes, int n_in,
                              void* d_out, int out_size) {
    const float* hs = (const float*)d_in[0];
    const float* Wc = (const float*)d_in[1];
    const float* bc = (const float*)d_in[2];
    const float* Wg = (const float*)d_in[3];
    const float* Wu = (const float*)d_in[4];
    const float* Wd = (const float*)d_in[5];
    float* out = (float*)d_out;

    cudaFuncSetAttribute(up_mma_kernel, cudaFuncAttributeMaxDynamicSharedMemorySize, U_SMEM);
    cudaFuncSetAttribute(down_mma_kernel, cudaFuncAttributeMaxDynamicSharedMemorySize, D_SMEM);

    init_kernel<<<1024, 256>>>(out, out_size);
    conv_x_kernel<<<2048, 256>>>(hs);

    __nv_bfloat16 *wg_h, *wg_l, *wu_h, *wu_l, *wd_h, *wd_l;
    cudaGetSymbolAddress((void**)&wg_h, g_wg_h);
    cudaGetSymbolAddress((void**)&wg_l, g_wg_l);
    cudaGetSymbolAddress((void**)&wu_h, g_wu_h);
    cudaGetSymbolAddress((void**)&wu_l, g_wu_l);
    cudaGetSymbolAddress((void**)&wd_h, g_wd_h);
    cudaGetSymbolAddress((void**)&wd_l, g_wd_l);

    dim3 tb(32, 8);
    transpose_split_kernel<<<dim3(IDIM / 32, DIM / 32, NE), tb>>>(Wg, wg_h, wg_l, DIM, IDIM);
    transpose_split_kernel<<<dim3(IDIM / 32, DIM / 32, NE), tb>>>(Wu, wu_h, wu_l, DIM, IDIM);
    transpose_split_kernel<<<dim3(DIM / 32, IDIM / 32, NE), tb>>>(Wd, wd_h, wd_l, IDIM, DIM);

    route_kernel<<<(NTOK * 32) / 256, 256>>>(hs, Wc, bc);

    up_mma_kernel<<<dim3(NTOK / 128, IDIM / 64, NE), 256, U_SMEM>>>();
    down_mma_kernel<<<dim3(NTOK / 128, DIM / 128, NE), 256, D_SMEM>>>(out);
}

// round 5
// speedup vs baseline: 3.4598x; 1.4601x over previous
#include <cuda_runtime.h>
#include <cuda_fp16.h>
#include <math.h>
#include <stdint.h>

#define NE 8
#define DIM 1024
#define IDIM 2048
#define NTOK 4096
#define ESTRIDE 4096

// ---------------- device scratch ----------------
__device__ int   g_count[NE];
__device__ int   g_rows[NE * ESTRIDE];
__device__ float g_w[NE * ESTRIDE];
__device__ __half g_xh[NTOK * DIM];
__device__ __half g_xl[NTOK * DIM];
__device__ __half g_wg[NE * IDIM * DIM];   // [e][i][d] K-major (K=d), single fp16
__device__ __half g_wu[NE * IDIM * DIM];
__device__ __half g_wd[NE * DIM * IDIM];   // [e][d][i] K-major (K=i)
__device__ __half g_hh[(size_t)NE * ESTRIDE * IDIM];
__device__ __half g_hl[(size_t)NE * ESTRIDE * IDIM];

// ---------------- helpers ----------------
__device__ __forceinline__ uint32_t smem_u32(const void* p) {
    uint32_t a;
    asm("{ .reg .u64 t; cvta.to.shared.u64 t, %1; cvt.u32.u64 %0, t; }"
        : "=r"(a) : "l"(p));
    return a;
}

#define LDSM4(r0, r1, r2, r3, addr)                                          \
    asm volatile("ldmatrix.sync.aligned.m8n8.x4.shared.b16 {%0,%1,%2,%3}, [%4];" \
                 : "=r"(r0), "=r"(r1), "=r"(r2), "=r"(r3) : "r"(addr))

#define MMA16816(c, a, b)                                                    \
    asm volatile("mma.sync.aligned.m16n8k16.row.col.f32.f16.f16.f32 "        \
                 "{%0,%1,%2,%3},{%4,%5,%6,%7},{%8,%9},{%0,%1,%2,%3};"        \
                 : "+f"((c)[0]), "+f"((c)[1]), "+f"((c)[2]), "+f"((c)[3])    \
                 : "r"((a)[0]), "r"((a)[1]), "r"((a)[2]), "r"((a)[3]),       \
                   "r"((b)[0]), "r"((b)[1]))

#define CPA16(dst, src, sz)                                                  \
    asm volatile("cp.async.cg.shared.global [%0], [%1], 16, %2;"             \
                 :: "r"(dst), "l"(src), "r"(sz) : "memory")
#define CP_COMMIT() asm volatile("cp.async.commit_group;" ::: "memory")
#define CP_WAIT(n)  asm volatile("cp.async.wait_group %0;" ::"n"(n) : "memory")

// ---------------- init ----------------
__global__ void init_kernel(float* __restrict__ out, int n) {
    int i = blockIdx.x * blockDim.x + threadIdx.x;
    if (i < NE) g_count[i] = 0;
    for (int j = i; j < n; j += gridDim.x * blockDim.x) out[j] = 0.0f;
}

// ---------------- x -> fp16 hi/lo (exact to ~22 bits) ----------------
__global__ void conv_x_kernel(const float* __restrict__ x) {
    int i = blockIdx.x * blockDim.x + threadIdx.x;
    const int N4 = NTOK * DIM / 4;
    for (int j = i; j < N4; j += gridDim.x * blockDim.x) {
        float4 v = reinterpret_cast<const float4*>(x)[j];
        __half h0 = __float2half_rn(v.x), h1 = __float2half_rn(v.y);
        __half h2 = __float2half_rn(v.z), h3 = __float2half_rn(v.w);
        __half hv[4] = {h0, h1, h2, h3};
        __half lv[4] = {
            __float2half_rn(v.x - __half2float(h0)),
            __float2half_rn(v.y - __half2float(h1)),
            __float2half_rn(v.z - __half2float(h2)),
            __float2half_rn(v.w - __half2float(h3))};
        reinterpret_cast<uint2*>(g_xh)[j] = *reinterpret_cast<uint2*>(hv);
        reinterpret_cast<uint2*>(g_xl)[j] = *reinterpret_cast<uint2*>(lv);
    }
}

// -------- transpose: in [E][R][C] fp32 -> out [E][C][R] fp16 --------
__global__ void transpose_half_kernel(const float* __restrict__ in,
                                      __half* __restrict__ oh,
                                      int R, int C) {
    __shared__ float t[32][33];
    int e = blockIdx.z;
    const float* ine = in + (size_t)e * R * C;
    int c0 = blockIdx.x * 32, r0 = blockIdx.y * 32;
    int x = threadIdx.x, y = threadIdx.y;  // 32 x 8
#pragma unroll
    for (int i = 0; i < 32; i += 8)
        t[y + i][x] = ine[(size_t)(r0 + y + i) * C + c0 + x];
    __syncthreads();
    __half* ohe = oh + (size_t)e * R * C;
#pragma unroll
    for (int i = 0; i < 32; i += 8)
        ohe[(size_t)(c0 + y + i) * R + r0 + x] = __float2half_rn(t[x][y + i]);
}

// ---------------- routing: one warp per token ----------------
__global__ void route_kernel(const float* __restrict__ x,
                             const float* __restrict__ Wc,
                             const float* __restrict__ bc) {
    int gwarp = (blockIdx.x * blockDim.x + threadIdx.x) >> 5;
    int lane = threadIdx.x & 31;
    if (gwarp >= NTOK) return;
    const float* xr = x + (size_t)gwarp * DIM;
    float acc[NE];
#pragma unroll
    for (int e = 0; e < NE; e++) acc[e] = 0.0f;
    for (int d = lane; d < DIM; d += 32) {
        float xv = xr[d];
#pragma unroll
        for (int e = 0; e < NE; e++) acc[e] += xv * Wc[e * DIM + d];
    }
#pragma unroll
    for (int e = 0; e < NE; e++)
#pragma unroll
        for (int off = 16; off > 0; off >>= 1)
            acc[e] += __shfl_xor_sync(0xffffffffu, acc[e], off);
    if (lane == 0) {
        float conf[NE];
#pragma unroll
        for (int e = 0; e < NE; e++)
            conf[e] = 1.0f / (1.0f + expf(-(acc[e] + bc[e])));
        int i0 = 0;
#pragma unroll
        for (int e = 1; e < NE; e++) if (conf[e] > conf[i0]) i0 = e;
        int i1 = -1;
#pragma unroll
        for (int e = 0; e < NE; e++) {
            if (e == i0) continue;
            if (i1 < 0 || conf[e] > conf[i1]) i1 = e;
        }
        float v0 = conf[i0], v1 = conf[i1];
        float w0 = 1.0f / (1.0f + expf(v1 - v0));
        float w1 = 1.0f / (1.0f + expf(v0 - v1));
        int p0 = atomicAdd(&g_count[i0], 1);
        g_rows[i0 * ESTRIDE + p0] = gwarp;
        g_w[i0 * ESTRIDE + p0] = w0;
        int p1 = atomicAdd(&g_count[i1], 1);
        g_rows[i1 * ESTRIDE + p1] = gwarp;
        g_w[i1 * ESTRIDE + p1] = w1;
    }
}

// =======================================================================
// Tiling constants. smem rows are 80B (40 halves) for conflict-free ldmatrix.
// =======================================================================
#define RBYTES  80          // bytes per smem row

// -------- up kernel smem stage layout (bytes) --------
#define U_AH  0
#define U_AL  10240         // 128*80
#define U_BG  20480         // 64*80
#define U_BU  25600
#define U_STAGE 30720
#define U_SMEM (2 * U_STAGE)

// -------- down kernel smem stage layout --------
#define D_AH  0
#define D_AL  10240
#define D_B   20480
#define D_STAGE 30720
#define D_SMEM (2 * D_STAGE)

// =======================================================================
// up: g = X*Wg^T, u = X*Wu^T  (X = Xh+Xl fp16 exact, W single fp16)
// CTA 128(M) x 64(N of IDIM), Kc=32; cp.async depth-2; h = silu(g)*u
// =======================================================================
__global__ __launch_bounds__(256)
void up_mma_kernel() {
    extern __shared__ char dsm[];
    __shared__ int stok[128];

    int e = blockIdx.z, m0 = blockIdx.x * 128, n0 = blockIdx.y * 64;
    int ne = g_count[e];
    if (m0 >= ne) return;
    int tid = threadIdx.x, wid = tid >> 5, l = tid & 31;
    if (tid < 128) stok[tid] = (m0 + tid < ne) ? g_rows[e * ESTRIDE + m0 + tid] : -1;
    __syncthreads();

    int wm = wid & 3, wn = wid >> 2;

    const __half* WG = g_wg + (size_t)e * IDIM * DIM;
    const __half* WU = g_wu + (size_t)e * IDIM * DIM;

    uint32_t sb = smem_u32(dsm);

    int arow0 = tid >> 2, ach = tid & 3;
    int brow = tid >> 2, bch = tid & 3;

    int lar = (l & 7) + 8 * ((l >> 3) & 1);
    int lac = 8 * (l >> 4);
    int lbr = (l & 7) + 8 * (l >> 4);
    int lbc = 8 * ((l >> 3) & 1);

    float cg[2][4][4], cu[2][4][4];
#pragma unroll
    for (int i = 0; i < 2; i++)
#pragma unroll
        for (int j = 0; j < 4; j++)
#pragma unroll
            for (int q = 0; q < 4; q++) { cg[i][j][q] = 0.f; cu[i][j][q] = 0.f; }

    const int NK = DIM / 32;

    auto load_stage = [&](int kc, int s) {
        uint32_t st = sb + s * U_STAGE;
        int k0 = kc * 32;
#pragma unroll
        for (int it = 0; it < 2; it++) {
            int row = arow0 + it * 64;
            int tok = stok[row];
            uint32_t sz = (tok >= 0) ? 16u : 0u;
            size_t go = (tok >= 0) ? ((size_t)tok * DIM + k0 + ach * 8) : 0;
            uint32_t so = row * RBYTES + ach * 16;
            CPA16(st + U_AH + so, g_xh + go, sz);
            CPA16(st + U_AL + so, g_xl + go, sz);
        }
        {
            size_t go = (size_t)(n0 + brow) * DIM + k0 + bch * 8;
            uint32_t so = brow * RBYTES + bch * 16;
            CPA16(st + U_BG + so, WG + go, 16u);
            CPA16(st + U_BU + so, WU + go, 16u);
        }
        CP_COMMIT();
    };

    load_stage(0, 0);

    for (int kc = 0; kc < NK; kc++) {
        if (kc + 1 < NK) load_stage(kc + 1, (kc + 1) & 1);
        if (kc + 1 < NK) { CP_WAIT(1); } else { CP_WAIT(0); }
        __syncthreads();

        uint32_t st = sb + (kc & 1) * U_STAGE;
#pragma unroll
        for (int ks = 0; ks < 2; ks++) {
            int kkb = ks * 32;
            uint32_t ah[2][4], al[2][4];
#pragma unroll
            for (int mf = 0; mf < 2; mf++) {
                uint32_t off = (uint32_t)((wm * 32 + mf * 16 + lar) * RBYTES + kkb + lac * 2);
                LDSM4(ah[mf][0], ah[mf][1], ah[mf][2], ah[mf][3], st + U_AH + off);
                LDSM4(al[mf][0], al[mf][1], al[mf][2], al[mf][3], st + U_AL + off);
            }
#pragma unroll
            for (int p = 0; p < 2; p++) {
                uint32_t off = (uint32_t)((wn * 32 + p * 16 + lbr) * RBYTES + kkb + lbc * 2);
                uint32_t bg[2][2], bu[2][2];
                LDSM4(bg[0][0], bg[0][1], bg[1][0], bg[1][1], st + U_BG + off);
                LDSM4(bu[0][0], bu[0][1], bu[1][0], bu[1][1], st + U_BU + off);
#pragma unroll
                for (int mf = 0; mf < 2; mf++)
#pragma unroll
                    for (int q = 0; q < 2; q++) {
                        int nf = 2 * p + q;
                        MMA16816(cg[mf][nf], ah[mf], bg[q]);
                        MMA16816(cg[mf][nf], al[mf], bg[q]);
                        MMA16816(cu[mf][nf], ah[mf], bu[q]);
                        MMA16816(cu[mf][nf], al[mf], bu[q]);
                    }
            }
        }
        __syncthreads();
    }

    // epilogue: h = silu(g) * u, split to fp16 hi/lo
    __half* hh = g_hh + (size_t)e * ESTRIDE * IDIM;
    __half* hl = g_hl + (size_t)e * ESTRIDE * IDIM;
#pragma unroll
    for (int mf = 0; mf < 2; mf++) {
        int r_lo = m0 + wm * 32 + mf * 16 + (l >> 2);
#pragma unroll
        for (int nf = 0; nf < 4; nf++) {
            int col = n0 + wn * 32 + nf * 8 + 2 * (l & 3);
#pragma unroll
            for (int half_ = 0; half_ < 2; half_++) {
                int r = r_lo + half_ * 8;
                if (r >= ne) continue;
                float gv0 = cg[mf][nf][half_ * 2 + 0], gv1 = cg[mf][nf][half_ * 2 + 1];
                float uv0 = cu[mf][nf][half_ * 2 + 0], uv1 = cu[mf][nf][half_ * 2 + 1];
                float h0 = uv0 * gv0 / (1.0f + expf(-gv0));
                float h1 = uv1 * gv1 / (1.0f + expf(-gv1));
                __half b0 = __float2half_rn(h0), b1 = __float2half_rn(h1);
                __half l0 = __float2half_rn(h0 - __half2float(b0));
                __half l1 = __float2half_rn(h1 - __half2float(b1));
                __half ph[2] = {b0, b1}, pl[2] = {l0, l1};
                size_t off = (size_t)r * IDIM + col;
                *reinterpret_cast<uint32_t*>(hh + off) = *reinterpret_cast<uint32_t*>(ph);
                *reinterpret_cast<uint32_t*>(hl + off) = *reinterpret_cast<uint32_t*>(pl);
            }
        }
    }
}

// =======================================================================
// down: Y = H*Wd^T (H = Hh+Hl fp16, Wd single fp16); out[token] += w * Y
// CTA 128(M) x 128(N of DIM), Kc=32 over K=2048; cp.async depth-2
// =======================================================================
__global__ __launch_bounds__(256)
void down_mma_kernel(float* __restrict__ out) {
    extern __shared__ char dsm[];

    int e = blockIdx.z, m0 = blockIdx.x * 128, n0 = blockIdx.y * 128;
    int ne = g_count[e];
    if (m0 >= ne) return;
    int tid = threadIdx.x, wid = tid >> 5, l = tid & 31;
    int wm = wid & 3, wn = wid >> 2;

    const __half* AH = g_hh + (size_t)e * ESTRIDE * IDIM;
    const __half* AL = g_hl + (size_t)e * ESTRIDE * IDIM;
    const __half* B  = g_wd + (size_t)e * DIM * IDIM;

    uint32_t sb = smem_u32(dsm);

    int row0 = tid >> 2, ch = tid & 3;

    int lar = (l & 7) + 8 * ((l >> 3) & 1);
    int lac = 8 * (l >> 4);
    int lbr = (l & 7) + 8 * (l >> 4);
    int lbc = 8 * ((l >> 3) & 1);

    float c[2][8][4];
#pragma unroll
    for (int i = 0; i < 2; i++)
#pragma unroll
        for (int j = 0; j < 8; j++)
#pragma unroll
            for (int q = 0; q < 4; q++) c[i][j][q] = 0.f;

    const int NK = IDIM / 32;

    auto load_stage = [&](int kc, int s) {
        uint32_t st = sb + s * D_STAGE;
        int k0 = kc * 32;
#pragma unroll
        for (int it = 0; it < 2; it++) {
            int row = row0 + it * 64;
            uint32_t so = row * RBYTES + ch * 16;
            uint32_t sz = (m0 + row < ne) ? 16u : 0u;
            size_t ga = (m0 + row < ne) ? ((size_t)(m0 + row) * IDIM + k0 + ch * 8) : 0;
            CPA16(st + D_AH + so, AH + ga, sz);
            CPA16(st + D_AL + so, AL + ga, sz);
            size_t gb = (size_t)(n0 + row) * IDIM + k0 + ch * 8;
            CPA16(st + D_B + so, B + gb, 16u);
        }
        CP_COMMIT();
    };

    load_stage(0, 0);

    for (int kc = 0; kc < NK; kc++) {
        if (kc + 1 < NK) load_stage(kc + 1, (kc + 1) & 1);
        if (kc + 1 < NK) { CP_WAIT(1); } else { CP_WAIT(0); }
        __syncthreads();

        uint32_t st = sb + (kc & 1) * D_STAGE;
#pragma unroll
        for (int ks = 0; ks < 2; ks++) {
            int kkb = ks * 32;
            uint32_t ah[2][4], al[2][4];
#pragma unroll
            for (int mf = 0; mf < 2; mf++) {
                uint32_t off = (uint32_t)((wm * 32 + mf * 16 + lar) * RBYTES + kkb + lac * 2);
                LDSM4(ah[mf][0], ah[mf][1], ah[mf][2], ah[mf][3], st + D_AH + off);
                LDSM4(al[mf][0], al[mf][1], al[mf][2], al[mf][3], st + D_AL + off);
            }
#pragma unroll
            for (int p = 0; p < 4; p++) {
                uint32_t off = (uint32_t)((wn * 64 + p * 16 + lbr) * RBYTES + kkb + lbc * 2);
                uint32_t bh[2][2];
                LDSM4(bh[0][0], bh[0][1], bh[1][0], bh[1][1], st + D_B + off);
#pragma unroll
                for (int mf = 0; mf < 2; mf++)
#pragma unroll
                    for (int q = 0; q < 2; q++) {
                        int nf = 2 * p + q;
                        MMA16816(c[mf][nf], ah[mf], bh[q]);
                        MMA16816(c[mf][nf], al[mf], bh[q]);
                    }
            }
        }
        __syncthreads();
    }

    // epilogue: weighted atomic combine
#pragma unroll
    for (int mf = 0; mf < 2; mf++) {
        int r_lo = m0 + wm * 32 + mf * 16 + (l >> 2);
#pragma unroll
        for (int half_ = 0; half_ < 2; half_++) {
            int r = r_lo + half_ * 8;
            if (r >= ne) continue;
            int   t = g_rows[e * ESTRIDE + r];
            float w = g_w[e * ESTRIDE + r];
            float* op = out + (size_t)t * DIM;
#pragma unroll
            for (int nf = 0; nf < 8; nf++) {
                int col = n0 + wn * 64 + nf * 8 + 2 * (l & 3);
                atomicAdd(op + col,     w * c[mf][nf][half_ * 2 + 0]);
                atomicAdd(op + col + 1, w * c[mf][nf][half_ * 2 + 1]);
            }
        }
    }
}

// ---------------- launcher ----------------
extern "C" void kernel_launch(void* const* d_in, const int* in_sizes, int n_in,
                              void* d_out, int out_size) {
    const float* hs = (const float*)d_in[0];
    const float* Wc = (const float*)d_in[1];
    const float* bc = (const float*)d_in[2];
    const float* Wg = (const float*)d_in[3];
    const float* Wu = (const float*)d_in[4];
    const float* Wd = (const float*)d_in[5];
    float* out = (float*)d_out;

    cudaFuncSetAttribute(up_mma_kernel, cudaFuncAttributeMaxDynamicSharedMemorySize, U_SMEM);
    cudaFuncSetAttribute(down_mma_kernel, cudaFuncAttributeMaxDynamicSharedMemorySize, D_SMEM);

    init_kernel<<<1024, 256>>>(out, out_size);
    conv_x_kernel<<<2048, 256>>>(hs);

    __half *wg, *wu, *wd;
    cudaGetSymbolAddress((void**)&wg, g_wg);
    cudaGetSymbolAddress((void**)&wu, g_wu);
    cudaGetSymbolAddress((void**)&wd, g_wd);

    dim3 tb(32, 8);
    transpose_half_kernel<<<dim3(IDIM / 32, DIM / 32, NE), tb>>>(Wg, wg, DIM, IDIM);
    transpose_half_kernel<<<dim3(IDIM / 32, DIM / 32, NE), tb>>>(Wu, wu, DIM, IDIM);
    transpose_half_kernel<<<dim3(DIM / 32, IDIM / 32, NE), tb>>>(Wd, wd, IDIM, DIM);

    route_kernel<<<(NTOK * 32) / 256, 256>>>(hs, Wc, bc);

    up_mma_kernel<<<dim3(NTOK / 128, IDIM / 64, NE), 256, U_SMEM>>>();
    down_mma_kernel<<<dim3(NTOK / 128, DIM / 128, NE), 256, D_SMEM>>>(out);
}

// round 6
// speedup vs baseline: 5.0129x; 1.4489x over previous
#include <cuda_runtime.h>
#include <cuda_fp16.h>
#include <math.h>
#include <stdint.h>

#define NE 8
#define DIM 1024
#define IDIM 2048
#define NTOK 4096
#define ESTRIDE 4096

// ---------------- device scratch ----------------
__device__ int   g_count[NE];
__device__ int   g_rows[NE * ESTRIDE];
__device__ float g_w[NE * ESTRIDE];
__device__ __half g_xh[NTOK * DIM];
__device__ __half g_wg[NE * IDIM * DIM];   // [e][i][d] K-major (K=d)
__device__ __half g_wu[NE * IDIM * DIM];
__device__ __half g_wd[NE * DIM * IDIM];   // [e][d][i] K-major (K=i)
__device__ __half g_hh[(size_t)NE * ESTRIDE * IDIM];

// ---------------- helpers ----------------
__device__ __forceinline__ uint32_t smem_u32(const void* p) {
    uint32_t a;
    asm("{ .reg .u64 t; cvta.to.shared.u64 t, %1; cvt.u32.u64 %0, t; }"
        : "=r"(a) : "l"(p));
    return a;
}

#define LDSM4(r0, r1, r2, r3, addr)                                          \
    asm volatile("ldmatrix.sync.aligned.m8n8.x4.shared.b16 {%0,%1,%2,%3}, [%4];" \
                 : "=r"(r0), "=r"(r1), "=r"(r2), "=r"(r3) : "r"(addr))

#define MMA16816(c, a, b)                                                    \
    asm volatile("mma.sync.aligned.m16n8k16.row.col.f32.f16.f16.f32 "        \
                 "{%0,%1,%2,%3},{%4,%5,%6,%7},{%8,%9},{%0,%1,%2,%3};"        \
                 : "+f"((c)[0]), "+f"((c)[1]), "+f"((c)[2]), "+f"((c)[3])    \
                 : "r"((a)[0]), "r"((a)[1]), "r"((a)[2]), "r"((a)[3]),       \
                   "r"((b)[0]), "r"((b)[1]))

#define CPA16(dst, src, sz)                                                  \
    asm volatile("cp.async.cg.shared.global [%0], [%1], 16, %2;"             \
                 :: "r"(dst), "l"(src), "r"(sz) : "memory")
#define CP_COMMIT() asm volatile("cp.async.commit_group;" ::: "memory")
#define CP_WAIT(n)  asm volatile("cp.async.wait_group %0;" ::"n"(n) : "memory")

// ---------------- init ----------------
__global__ void init_kernel(float* __restrict__ out, int n) {
    int i = blockIdx.x * blockDim.x + threadIdx.x;
    if (i < NE) g_count[i] = 0;
    for (int j = i; j < n; j += gridDim.x * blockDim.x) out[j] = 0.0f;
}

// ---------------- x -> fp16 ----------------
__global__ void conv_x_kernel(const float* __restrict__ x) {
    int i = blockIdx.x * blockDim.x + threadIdx.x;
    const int N4 = NTOK * DIM / 4;
    for (int j = i; j < N4; j += gridDim.x * blockDim.x) {
        float4 v = reinterpret_cast<const float4*>(x)[j];
        __half hv[4] = {__float2half_rn(v.x), __float2half_rn(v.y),
                        __float2half_rn(v.z), __float2half_rn(v.w)};
        reinterpret_cast<uint2*>(g_xh)[j] = *reinterpret_cast<uint2*>(hv);
    }
}

// -------- transpose: in [E][R][C] fp32 -> out [E][C][R] fp16 --------
__global__ void transpose_half_kernel(const float* __restrict__ in,
                                      __half* __restrict__ oh,
                                      int R, int C) {
    __shared__ float t[32][33];
    int e = blockIdx.z;
    const float* ine = in + (size_t)e * R * C;
    int c0 = blockIdx.x * 32, r0 = blockIdx.y * 32;
    int x = threadIdx.x, y = threadIdx.y;  // 32 x 8
#pragma unroll
    for (int i = 0; i < 32; i += 8)
        t[y + i][x] = ine[(size_t)(r0 + y + i) * C + c0 + x];
    __syncthreads();
    __half* ohe = oh + (size_t)e * R * C;
#pragma unroll
    for (int i = 0; i < 32; i += 8)
        ohe[(size_t)(c0 + y + i) * R + r0 + x] = __float2half_rn(t[x][y + i]);
}

// ---------------- routing: one warp per token ----------------
__global__ void route_kernel(const float* __restrict__ x,
                             const float* __restrict__ Wc,
                             const float* __restrict__ bc) {
    int gwarp = (blockIdx.x * blockDim.x + threadIdx.x) >> 5;
    int lane = threadIdx.x & 31;
    if (gwarp >= NTOK) return;
    const float* xr = x + (size_t)gwarp * DIM;
    float acc[NE];
#pragma unroll
    for (int e = 0; e < NE; e++) acc[e] = 0.0f;
    for (int d = lane; d < DIM; d += 32) {
        float xv = xr[d];
#pragma unroll
        for (int e = 0; e < NE; e++) acc[e] += xv * Wc[e * DIM + d];
    }
#pragma unroll
    for (int e = 0; e < NE; e++)
#pragma unroll
        for (int off = 16; off > 0; off >>= 1)
            acc[e] += __shfl_xor_sync(0xffffffffu, acc[e], off);
    if (lane == 0) {
        float conf[NE];
#pragma unroll
        for (int e = 0; e < NE; e++)
            conf[e] = 1.0f / (1.0f + expf(-(acc[e] + bc[e])));
        int i0 = 0;
#pragma unroll
        for (int e = 1; e < NE; e++) if (conf[e] > conf[i0]) i0 = e;
        int i1 = -1;
#pragma unroll
        for (int e = 0; e < NE; e++) {
            if (e == i0) continue;
            if (i1 < 0 || conf[e] > conf[i1]) i1 = e;
        }
        float v0 = conf[i0], v1 = conf[i1];
        float w0 = 1.0f / (1.0f + expf(v1 - v0));
        float w1 = 1.0f / (1.0f + expf(v0 - v1));
        int p0 = atomicAdd(&g_count[i0], 1);
        g_rows[i0 * ESTRIDE + p0] = gwarp;
        g_w[i0 * ESTRIDE + p0] = w0;
        int p1 = atomicAdd(&g_count[i1], 1);
        g_rows[i1 * ESTRIDE + p1] = gwarp;
        g_w[i1 * ESTRIDE + p1] = w1;
    }
}

// =======================================================================
// Tiling constants. smem rows are 80B (40 halves) for conflict-free ldmatrix.
// =======================================================================
#define RBYTES  80          // bytes per smem row

// -------- up kernel smem stage layout (bytes) --------
#define U_A   0             // 128*80 = 10240
#define U_BG  10240         // 64*80 = 5120
#define U_BU  15360
#define U_STAGE 20480
#define U_SMEM (2 * U_STAGE)

// -------- down kernel smem stage layout --------
#define D_A   0             // 128*80
#define D_B   10240         // 128*80
#define D_STAGE 20480
#define D_SMEM (2 * D_STAGE)

// =======================================================================
// up: g = X*Wg^T, u = X*Wu^T (fp16 in, fp32 accum); h = silu(g)*u -> fp16
// CTA 128(M) x 64(N of IDIM), Kc=32; cp.async depth-2
// =======================================================================
__global__ __launch_bounds__(256)
void up_mma_kernel() {
    extern __shared__ char dsm[];
    __shared__ int stok[128];

    int e = blockIdx.z, m0 = blockIdx.x * 128, n0 = blockIdx.y * 64;
    int ne = g_count[e];
    if (m0 >= ne) return;
    int tid = threadIdx.x, wid = tid >> 5, l = tid & 31;
    if (tid < 128) stok[tid] = (m0 + tid < ne) ? g_rows[e * ESTRIDE + m0 + tid] : -1;
    __syncthreads();

    int wm = wid & 3, wn = wid >> 2;

    const __half* WG = g_wg + (size_t)e * IDIM * DIM;
    const __half* WU = g_wu + (size_t)e * IDIM * DIM;

    uint32_t sb = smem_u32(dsm);

    int arow0 = tid >> 2, ach = tid & 3;
    int brow = tid >> 2, bch = tid & 3;

    int lar = (l & 7) + 8 * ((l >> 3) & 1);
    int lac = 8 * (l >> 4);
    int lbr = (l & 7) + 8 * (l >> 4);
    int lbc = 8 * ((l >> 3) & 1);

    float cg[2][4][4], cu[2][4][4];
#pragma unroll
    for (int i = 0; i < 2; i++)
#pragma unroll
        for (int j = 0; j < 4; j++)
#pragma unroll
            for (int q = 0; q < 4; q++) { cg[i][j][q] = 0.f; cu[i][j][q] = 0.f; }

    const int NK = DIM / 32;

    auto load_stage = [&](int kc, int s) {
        uint32_t st = sb + s * U_STAGE;
        int k0 = kc * 32;
#pragma unroll
        for (int it = 0; it < 2; it++) {
            int row = arow0 + it * 64;
            int tok = stok[row];
            uint32_t sz = (tok >= 0) ? 16u : 0u;
            size_t go = (tok >= 0) ? ((size_t)tok * DIM + k0 + ach * 8) : 0;
            CPA16(st + U_A + row * RBYTES + ach * 16, g_xh + go, sz);
        }
        {
            size_t go = (size_t)(n0 + brow) * DIM + k0 + bch * 8;
            uint32_t so = brow * RBYTES + bch * 16;
            CPA16(st + U_BG + so, WG + go, 16u);
            CPA16(st + U_BU + so, WU + go, 16u);
        }
        CP_COMMIT();
    };

    load_stage(0, 0);

    for (int kc = 0; kc < NK; kc++) {
        if (kc + 1 < NK) load_stage(kc + 1, (kc + 1) & 1);
        if (kc + 1 < NK) { CP_WAIT(1); } else { CP_WAIT(0); }
        __syncthreads();

        uint32_t st = sb + (kc & 1) * U_STAGE;
#pragma unroll
        for (int ks = 0; ks < 2; ks++) {
            int kkb = ks * 32;
            uint32_t ah[2][4];
#pragma unroll
            for (int mf = 0; mf < 2; mf++) {
                uint32_t off = (uint32_t)((wm * 32 + mf * 16 + lar) * RBYTES + kkb + lac * 2);
                LDSM4(ah[mf][0], ah[mf][1], ah[mf][2], ah[mf][3], st + U_A + off);
            }
#pragma unroll
            for (int p = 0; p < 2; p++) {
                uint32_t off = (uint32_t)((wn * 32 + p * 16 + lbr) * RBYTES + kkb + lbc * 2);
                uint32_t bg[2][2], bu[2][2];
                LDSM4(bg[0][0], bg[0][1], bg[1][0], bg[1][1], st + U_BG + off);
                LDSM4(bu[0][0], bu[0][1], bu[1][0], bu[1][1], st + U_BU + off);
#pragma unroll
                for (int mf = 0; mf < 2; mf++)
#pragma unroll
                    for (int q = 0; q < 2; q++) {
                        int nf = 2 * p + q;
                        MMA16816(cg[mf][nf], ah[mf], bg[q]);
                        MMA16816(cu[mf][nf], ah[mf], bu[q]);
                    }
            }
        }
        __syncthreads();
    }

    // epilogue: h = silu(g) * u -> fp16
    __half* hh = g_hh + (size_t)e * ESTRIDE * IDIM;
#pragma unroll
    for (int mf = 0; mf < 2; mf++) {
        int r_lo = m0 + wm * 32 + mf * 16 + (l >> 2);
#pragma unroll
        for (int nf = 0; nf < 4; nf++) {
            int col = n0 + wn * 32 + nf * 8 + 2 * (l & 3);
#pragma unroll
            for (int half_ = 0; half_ < 2; half_++) {
                int r = r_lo + half_ * 8;
                if (r >= ne) continue;
                float gv0 = cg[mf][nf][half_ * 2 + 0], gv1 = cg[mf][nf][half_ * 2 + 1];
                float uv0 = cu[mf][nf][half_ * 2 + 0], uv1 = cu[mf][nf][half_ * 2 + 1];
                float h0 = uv0 * gv0 / (1.0f + expf(-gv0));
                float h1 = uv1 * gv1 / (1.0f + expf(-gv1));
                __half ph[2] = {__float2half_rn(h0), __float2half_rn(h1)};
                *reinterpret_cast<uint32_t*>(hh + (size_t)r * IDIM + col) =
                    *reinterpret_cast<uint32_t*>(ph);
            }
        }
    }
}

// =======================================================================
// down: Y = H*Wd^T (fp16 in, fp32 accum); out[token] += w * Y
// CTA 128(M) x 128(N of DIM), Kc=32 over K=2048; cp.async depth-2
// =======================================================================
__global__ __launch_bounds__(256)
void down_mma_kernel(float* __restrict__ out) {
    extern __shared__ char dsm[];

    int e = blockIdx.z, m0 = blockIdx.x * 128, n0 = blockIdx.y * 128;
    int ne = g_count[e];
    if (m0 >= ne) return;
    int tid = threadIdx.x, wid = tid >> 5, l = tid & 31;
    int wm = wid & 3, wn = wid >> 2;

    const __half* AH = g_hh + (size_t)e * ESTRIDE * IDIM;
    const __half* B  = g_wd + (size_t)e * DIM * IDIM;

    uint32_t sb = smem_u32(dsm);

    int row0 = tid >> 2, ch = tid & 3;

    int lar = (l & 7) + 8 * ((l >> 3) & 1);
    int lac = 8 * (l >> 4);
    int lbr = (l & 7) + 8 * (l >> 4);
    int lbc = 8 * ((l >> 3) & 1);

    float c[2][8][4];
#pragma unroll
    for (int i = 0; i < 2; i++)
#pragma unroll
        for (int j = 0; j < 8; j++)
#pragma unroll
            for (int q = 0; q < 4; q++) c[i][j][q] = 0.f;

    const int NK = IDIM / 32;

    auto load_stage = [&](int kc, int s) {
        uint32_t st = sb + s * D_STAGE;
        int k0 = kc * 32;
#pragma unroll
        for (int it = 0; it < 2; it++) {
            int row = row0 + it * 64;
            uint32_t so = row * RBYTES + ch * 16;
            uint32_t sz = (m0 + row < ne) ? 16u : 0u;
            size_t ga = (m0 + row < ne) ? ((size_t)(m0 + row) * IDIM + k0 + ch * 8) : 0;
            CPA16(st + D_A + so, AH + ga, sz);
            size_t gb = (size_t)(n0 + row) * IDIM + k0 + ch * 8;
            CPA16(st + D_B + so, B + gb, 16u);
        }
        CP_COMMIT();
    };

    load_stage(0, 0);

    for (int kc = 0; kc < NK; kc++) {
        if (kc + 1 < NK) load_stage(kc + 1, (kc + 1) & 1);
        if (kc + 1 < NK) { CP_WAIT(1); } else { CP_WAIT(0); }
        __syncthreads();

        uint32_t st = sb + (kc & 1) * D_STAGE;
#pragma unroll
        for (int ks = 0; ks < 2; ks++) {
            int kkb = ks * 32;
            uint32_t ah[2][4];
#pragma unroll
            for (int mf = 0; mf < 2; mf++) {
                uint32_t off = (uint32_t)((wm * 32 + mf * 16 + lar) * RBYTES + kkb + lac * 2);
                LDSM4(ah[mf][0], ah[mf][1], ah[mf][2], ah[mf][3], st + D_A + off);
            }
#pragma unroll
            for (int p = 0; p < 4; p++) {
                uint32_t off = (uint32_t)((wn * 64 + p * 16 + lbr) * RBYTES + kkb + lbc * 2);
                uint32_t bh[2][2];
                LDSM4(bh[0][0], bh[0][1], bh[1][0], bh[1][1], st + D_B + off);
#pragma unroll
                for (int mf = 0; mf < 2; mf++)
#pragma unroll
                    for (int q = 0; q < 2; q++)
                        MMA16816(c[mf][2 * p + q], ah[mf], bh[q]);
            }
        }
        __syncthreads();
    }

    // epilogue: weighted atomic combine
#pragma unroll
    for (int mf = 0; mf < 2; mf++) {
        int r_lo = m0 + wm * 32 + mf * 16 + (l >> 2);
#pragma unroll
        for (int half_ = 0; half_ < 2; half_++) {
            int r = r_lo + half_ * 8;
            if (r >= ne) continue;
            int   t = g_rows[e * ESTRIDE + r];
            float w = g_w[e * ESTRIDE + r];
            float* op = out + (size_t)t * DIM;
#pragma unroll
            for (int nf = 0; nf < 8; nf++) {
                int col = n0 + wn * 64 + nf * 8 + 2 * (l & 3);
                atomicAdd(op + col,     w * c[mf][nf][half_ * 2 + 0]);
                atomicAdd(op + col + 1, w * c[mf][nf][half_ * 2 + 1]);
            }
        }
    }
}

// ---------------- launcher ----------------
extern "C" void kernel_launch(void* const* d_in, const int* in_sizes, int n_in,
                              void* d_out, int out_size) {
    const float* hs = (const float*)d_in[0];
    const float* Wc = (const float*)d_in[1];
    const float* bc = (const float*)d_in[2];
    const float* Wg = (const float*)d_in[3];
    const float* Wu = (const float*)d_in[4];
    const float* Wd = (const float*)d_in[5];
    float* out = (float*)d_out;

    cudaFuncSetAttribute(up_mma_kernel, cudaFuncAttributeMaxDynamicSharedMemorySize, U_SMEM);
    cudaFuncSetAttribute(down_mma_kernel, cudaFuncAttributeMaxDynamicSharedMemorySize, D_SMEM);

    init_kernel<<<1024, 256>>>(out, out_size);
    conv_x_kernel<<<2048, 256>>>(hs);

    __half *wg, *wu, *wd;
    cudaGetSymbolAddress((void**)&wg, g_wg);
    cudaGetSymbolAddress((void**)&wu, g_wu);
    cudaGetSymbolAddress((void**)&wd, g_wd);

    dim3 tb(32, 8);
    transpose_half_kernel<<<dim3(IDIM / 32, DIM / 32, NE), tb>>>(Wg, wg, DIM, IDIM);
    transpose_half_kernel<<<dim3(IDIM / 32, DIM / 32, NE), tb>>>(Wu, wu, DIM, IDIM);
    transpose_half_kernel<<<dim3(DIM / 32, IDIM / 32, NE), tb>>>(Wd, wd, IDIM, DIM);

    route_kernel<<<(NTOK * 32) / 256, 256>>>(hs, Wc, bc);

    up_mma_kernel<<<dim3(NTOK / 128, IDIM / 64, NE), 256, U_SMEM>>>();
    down_mma_kernel<<<dim3(NTOK / 128, DIM / 128, NE), 256, D_SMEM>>>(out);
}

// round 7
// speedup vs baseline: 5.7406x; 1.1452x over previous
#include <cuda_runtime.h>
#include <cuda_fp16.h>
#include <math.h>
#include <stdint.h>

#define NE 8
#define DIM 1024
#define IDIM 2048
#define NTOK 4096
#define ESTRIDE 4096

// ---------------- device scratch ----------------
__device__ int   g_count[NE];
__device__ int   g_rows[NE * ESTRIDE];
__device__ float g_w[NE * ESTRIDE];
__device__ __half g_xh[NTOK * DIM];
__device__ __half g_wg[NE * IDIM * DIM];   // [e][i][d] K-major (K=d)
__device__ __half g_wu[NE * IDIM * DIM];
__device__ __half g_wd[NE * DIM * IDIM];   // [e][d][i] K-major (K=i)
__device__ __half g_hh[(size_t)NE * ESTRIDE * IDIM];

// ---------------- helpers ----------------
__device__ __forceinline__ uint32_t smem_u32(const void* p) {
    uint32_t a;
    asm("{ .reg .u64 t; cvta.to.shared.u64 t, %1; cvt.u32.u64 %0, t; }"
        : "=r"(a) : "l"(p));
    return a;
}

#define LDSM4(r0, r1, r2, r3, addr)                                          \
    asm volatile("ldmatrix.sync.aligned.m8n8.x4.shared.b16 {%0,%1,%2,%3}, [%4];" \
                 : "=r"(r0), "=r"(r1), "=r"(r2), "=r"(r3) : "r"(addr))

#define MMA16816(c, a, b)                                                    \
    asm volatile("mma.sync.aligned.m16n8k16.row.col.f32.f16.f16.f32 "        \
                 "{%0,%1,%2,%3},{%4,%5,%6,%7},{%8,%9},{%0,%1,%2,%3};"        \
                 : "+f"((c)[0]), "+f"((c)[1]), "+f"((c)[2]), "+f"((c)[3])    \
                 : "r"((a)[0]), "r"((a)[1]), "r"((a)[2]), "r"((a)[3]),       \
                   "r"((b)[0]), "r"((b)[1]))

#define CPA16(dst, src, sz)                                                  \
    asm volatile("cp.async.cg.shared.global [%0], [%1], 16, %2;"             \
                 :: "r"(dst), "l"(src), "r"(sz) : "memory")
#define CP_COMMIT() asm volatile("cp.async.commit_group;" ::: "memory")
#define CP_WAIT(n)  asm volatile("cp.async.wait_group %0;" ::"n"(n) : "memory")

// ---------------- init ----------------
__global__ void init_kernel(float* __restrict__ out, int n) {
    int i = blockIdx.x * blockDim.x + threadIdx.x;
    if (i < NE) g_count[i] = 0;
    for (int j = i; j < n; j += gridDim.x * blockDim.x) out[j] = 0.0f;
}

// ---------------- x -> fp16 ----------------
__global__ void conv_x_kernel(const float* __restrict__ x) {
    int i = blockIdx.x * blockDim.x + threadIdx.x;
    const int N4 = NTOK * DIM / 4;
    for (int j = i; j < N4; j += gridDim.x * blockDim.x) {
        float4 v = reinterpret_cast<const float4*>(x)[j];
        __half hv[4] = {__float2half_rn(v.x), __float2half_rn(v.y),
                        __float2half_rn(v.z), __float2half_rn(v.w)};
        reinterpret_cast<uint2*>(g_xh)[j] = *reinterpret_cast<uint2*>(hv);
    }
}

// -------- transpose: in [E][R][C] fp32 -> out [E][C][R] fp16 --------
// 32(C) x 64(R) tiles: output rows write 64 fp16 = 128B full lines.
__global__ void transpose_half_kernel(const float* __restrict__ in,
                                      __half* __restrict__ oh,
                                      int R, int C) {
    __shared__ float t[32][65];   // [c][r]
    int e = blockIdx.z;
    const float* ine = in + (size_t)e * R * C;
    int c0 = blockIdx.x * 32, r0 = blockIdx.y * 64;
    int tid = threadIdx.x;
    int cx = tid & 31, ry = tid >> 5;    // load: 32 c-lanes x 8 r-groups
#pragma unroll
    for (int i = 0; i < 64; i += 8)
        t[cx][ry + i] = ine[(size_t)(r0 + ry + i) * C + c0 + cx];
    __syncthreads();
    __half* ohe = oh + (size_t)e * R * C;
    int rx = tid & 63, cy = tid >> 6;    // store: 64 r-lanes x 4 c-groups
#pragma unroll
    for (int j = 0; j < 32; j += 4)
        ohe[(size_t)(c0 + cy + j) * R + r0 + rx] = __float2half_rn(t[cy + j][rx]);
}

// ---------------- routing: one warp per token ----------------
__global__ void route_kernel(const float* __restrict__ x,
                             const float* __restrict__ Wc,
                             const float* __restrict__ bc) {
    int gwarp = (blockIdx.x * blockDim.x + threadIdx.x) >> 5;
    int lane = threadIdx.x & 31;
    if (gwarp >= NTOK) return;
    const float* xr = x + (size_t)gwarp * DIM;
    float acc[NE];
#pragma unroll
    for (int e = 0; e < NE; e++) acc[e] = 0.0f;
    for (int d = lane; d < DIM; d += 32) {
        float xv = xr[d];
#pragma unroll
        for (int e = 0; e < NE; e++) acc[e] += xv * Wc[e * DIM + d];
    }
#pragma unroll
    for (int e = 0; e < NE; e++)
#pragma unroll
        for (int off = 16; off > 0; off >>= 1)
            acc[e] += __shfl_xor_sync(0xffffffffu, acc[e], off);
    if (lane == 0) {
        float conf[NE];
#pragma unroll
        for (int e = 0; e < NE; e++)
            conf[e] = 1.0f / (1.0f + expf(-(acc[e] + bc[e])));
        int i0 = 0;
#pragma unroll
        for (int e = 1; e < NE; e++) if (conf[e] > conf[i0]) i0 = e;
        int i1 = -1;
#pragma unroll
        for (int e = 0; e < NE; e++) {
            if (e == i0) continue;
            if (i1 < 0 || conf[e] > conf[i1]) i1 = e;
        }
        float v0 = conf[i0], v1 = conf[i1];
        float w0 = 1.0f / (1.0f + expf(v1 - v0));
        float w1 = 1.0f / (1.0f + expf(v0 - v1));
        int p0 = atomicAdd(&g_count[i0], 1);
        g_rows[i0 * ESTRIDE + p0] = gwarp;
        g_w[i0 * ESTRIDE + p0] = w0;
        int p1 = atomicAdd(&g_count[i1], 1);
        g_rows[i1 * ESTRIDE + p1] = gwarp;
        g_w[i1 * ESTRIDE + p1] = w1;
    }
}

// =======================================================================
// Tiling: Kc=64, rows padded to 144B (64 halves + 8 pad) — 144/16=9 is
// coprime with 8 -> conflict-free ldmatrix.
// =======================================================================
#define RBYTES  144

// -------- up kernel smem stage layout (bytes) --------
#define U_A   0                 // 128*144 = 18432
#define U_BG  18432             // 64*144 = 9216
#define U_BU  27648
#define U_STAGE 36864
#define U_SMEM (2 * U_STAGE)

// -------- down kernel smem stage layout --------
#define D_A   0                 // 128*144
#define D_B   18432             // 128*144
#define D_STAGE 36864
#define D_SMEM (2 * D_STAGE)

// =======================================================================
// up: g = X*Wg^T, u = X*Wu^T (fp16 in, fp32 accum); h = silu(g)*u -> fp16
// CTA 128(M) x 64(N of IDIM), Kc=64; cp.async depth-2
// =======================================================================
__global__ __launch_bounds__(256)
void up_mma_kernel() {
    extern __shared__ char dsm[];
    __shared__ int stok[128];

    int e = blockIdx.z, m0 = blockIdx.x * 128, n0 = blockIdx.y * 64;
    int ne = g_count[e];
    if (m0 >= ne) return;
    int tid = threadIdx.x, wid = tid >> 5, l = tid & 31;
    if (tid < 128) stok[tid] = (m0 + tid < ne) ? g_rows[e * ESTRIDE + m0 + tid] : -1;
    __syncthreads();

    int wm = wid & 3, wn = wid >> 2;

    const __half* WG = g_wg + (size_t)e * IDIM * DIM;
    const __half* WU = g_wu + (size_t)e * IDIM * DIM;

    uint32_t sb = smem_u32(dsm);

    // loads: row = idx>>3 (8 x 16B chunks per 128B row), ch = idx&7
    int lrow = tid >> 3, lch = tid & 7;

    int lar = (l & 7) + 8 * ((l >> 3) & 1);
    int lac = 8 * (l >> 4);
    int lbr = (l & 7) + 8 * (l >> 4);
    int lbc = 8 * ((l >> 3) & 1);

    float cg[2][4][4], cu[2][4][4];
#pragma unroll
    for (int i = 0; i < 2; i++)
#pragma unroll
        for (int j = 0; j < 4; j++)
#pragma unroll
            for (int q = 0; q < 4; q++) { cg[i][j][q] = 0.f; cu[i][j][q] = 0.f; }

    const int NK = DIM / 64;

    auto load_stage = [&](int kc, int s) {
        uint32_t st = sb + s * U_STAGE;
        int k0 = kc * 64;
        // A: 128 rows x 8 chunks = 1024 ops, 4 per thread
#pragma unroll
        for (int it = 0; it < 4; it++) {
            int row = lrow + it * 32;
            int tok = stok[row];
            uint32_t sz = (tok >= 0) ? 16u : 0u;
            size_t go = (tok >= 0) ? ((size_t)tok * DIM + k0 + lch * 8) : 0;
            CPA16(st + U_A + row * RBYTES + lch * 16, g_xh + go, sz);
        }
        // Bg/Bu: 64 rows x 8 chunks = 512 ops each, 2 per thread
#pragma unroll
        for (int it = 0; it < 2; it++) {
            int row = lrow + it * 32;
            size_t go = (size_t)(n0 + row) * DIM + k0 + lch * 8;
            uint32_t so = row * RBYTES + lch * 16;
            CPA16(st + U_BG + so, WG + go, 16u);
            CPA16(st + U_BU + so, WU + go, 16u);
        }
        CP_COMMIT();
    };

    load_stage(0, 0);

    for (int kc = 0; kc < NK; kc++) {
        if (kc + 1 < NK) { load_stage(kc + 1, (kc + 1) & 1); CP_WAIT(1); }
        else             { CP_WAIT(0); }
        __syncthreads();

        uint32_t st = sb + (kc & 1) * U_STAGE;
#pragma unroll
        for (int ks = 0; ks < 4; ks++) {
            int kkb = ks * 32;
            uint32_t ah[2][4];
#pragma unroll
            for (int mf = 0; mf < 2; mf++) {
                uint32_t off = (uint32_t)((wm * 32 + mf * 16 + lar) * RBYTES + kkb + lac * 2);
                LDSM4(ah[mf][0], ah[mf][1], ah[mf][2], ah[mf][3], st + U_A + off);
            }
#pragma unroll
            for (int p = 0; p < 2; p++) {
                uint32_t off = (uint32_t)((wn * 32 + p * 16 + lbr) * RBYTES + kkb + lbc * 2);
                uint32_t bg[2][2], bu[2][2];
                LDSM4(bg[0][0], bg[0][1], bg[1][0], bg[1][1], st + U_BG + off);
                LDSM4(bu[0][0], bu[0][1], bu[1][0], bu[1][1], st + U_BU + off);
#pragma unroll
                for (int mf = 0; mf < 2; mf++)
#pragma unroll
                    for (int q = 0; q < 2; q++) {
                        int nf = 2 * p + q;
                        MMA16816(cg[mf][nf], ah[mf], bg[q]);
                        MMA16816(cu[mf][nf], ah[mf], bu[q]);
                    }
            }
        }
        __syncthreads();
    }

    // epilogue: h = silu(g) * u -> fp16
    __half* hh = g_hh + (size_t)e * ESTRIDE * IDIM;
#pragma unroll
    for (int mf = 0; mf < 2; mf++) {
        int r_lo = m0 + wm * 32 + mf * 16 + (l >> 2);
#pragma unroll
        for (int nf = 0; nf < 4; nf++) {
            int col = n0 + wn * 32 + nf * 8 + 2 * (l & 3);
#pragma unroll
            for (int half_ = 0; half_ < 2; half_++) {
                int r = r_lo + half_ * 8;
                if (r >= ne) continue;
                float gv0 = cg[mf][nf][half_ * 2 + 0], gv1 = cg[mf][nf][half_ * 2 + 1];
                float uv0 = cu[mf][nf][half_ * 2 + 0], uv1 = cu[mf][nf][half_ * 2 + 1];
                float h0 = uv0 * gv0 / (1.0f + expf(-gv0));
                float h1 = uv1 * gv1 / (1.0f + expf(-gv1));
                __half ph[2] = {__float2half_rn(h0), __float2half_rn(h1)};
                *reinterpret_cast<uint32_t*>(hh + (size_t)r * IDIM + col) =
                    *reinterpret_cast<uint32_t*>(ph);
            }
        }
    }
}

// =======================================================================
// down: Y = H*Wd^T (fp16 in, fp32 accum); out[token] += w * Y
// CTA 128(M) x 128(N of DIM), Kc=64 over K=2048; cp.async depth-2
// =======================================================================
__global__ __launch_bounds__(256)
void down_mma_kernel(float* __restrict__ out) {
    extern __shared__ char dsm[];

    int e = blockIdx.z, m0 = blockIdx.x * 128, n0 = blockIdx.y * 128;
    int ne = g_count[e];
    if (m0 >= ne) return;
    int tid = threadIdx.x, wid = tid >> 5, l = tid & 31;
    int wm = wid & 3, wn = wid >> 2;

    const __half* AH = g_hh + (size_t)e * ESTRIDE * IDIM;
    const __half* B  = g_wd + (size_t)e * DIM * IDIM;

    uint32_t sb = smem_u32(dsm);

    int lrow = tid >> 3, lch = tid & 7;

    int lar = (l & 7) + 8 * ((l >> 3) & 1);
    int lac = 8 * (l >> 4);
    int lbr = (l & 7) + 8 * (l >> 4);
    int lbc = 8 * ((l >> 3) & 1);

    float c[2][8][4];
#pragma unroll
    for (int i = 0; i < 2; i++)
#pragma unroll
        for (int j = 0; j < 8; j++)
#pragma unroll
            for (int q = 0; q < 4; q++) c[i][j][q] = 0.f;

    const int NK = IDIM / 64;

    auto load_stage = [&](int kc, int s) {
        uint32_t st = sb + s * D_STAGE;
        int k0 = kc * 64;
#pragma unroll
        for (int it = 0; it < 4; it++) {
            int row = lrow + it * 32;
            uint32_t so = row * RBYTES + lch * 16;
            uint32_t sz = (m0 + row < ne) ? 16u : 0u;
            size_t ga = (m0 + row < ne) ? ((size_t)(m0 + row) * IDIM + k0 + lch * 8) : 0;
            CPA16(st + D_A + so, AH + ga, sz);
            size_t gb = (size_t)(n0 + row) * IDIM + k0 + lch * 8;
            CPA16(st + D_B + so, B + gb, 16u);
        }
        CP_COMMIT();
    };

    load_stage(0, 0);

    for (int kc = 0; kc < NK; kc++) {
        if (kc + 1 < NK) { load_stage(kc + 1, (kc + 1) & 1); CP_WAIT(1); }
        else             { CP_WAIT(0); }
        __syncthreads();

        uint32_t st = sb + (kc & 1) * D_STAGE;
#pragma unroll
        for (int ks = 0; ks < 4; ks++) {
            int kkb = ks * 32;
            uint32_t ah[2][4];
#pragma unroll
            for (int mf = 0; mf < 2; mf++) {
                uint32_t off = (uint32_t)((wm * 32 + mf * 16 + lar) * RBYTES + kkb + lac * 2);
                LDSM4(ah[mf][0], ah[mf][1], ah[mf][2], ah[mf][3], st + D_A + off);
            }
#pragma unroll
            for (int p = 0; p < 4; p++) {
                uint32_t off = (uint32_t)((wn * 64 + p * 16 + lbr) * RBYTES + kkb + lbc * 2);
                uint32_t bh[2][2];
                LDSM4(bh[0][0], bh[0][1], bh[1][0], bh[1][1], st + D_B + off);
#pragma unroll
                for (int mf = 0; mf < 2; mf++)
#pragma unroll
                    for (int q = 0; q < 2; q++)
                        MMA16816(c[mf][2 * p + q], ah[mf], bh[q]);
            }
        }
        __syncthreads();
    }

    // epilogue: weighted atomic combine
#pragma unroll
    for (int mf = 0; mf < 2; mf++) {
        int r_lo = m0 + wm * 32 + mf * 16 + (l >> 2);
#pragma unroll
        for (int half_ = 0; half_ < 2; half_++) {
            int r = r_lo + half_ * 8;
            if (r >= ne) continue;
            int   t = g_rows[e * ESTRIDE + r];
            float w = g_w[e * ESTRIDE + r];
            float* op = out + (size_t)t * DIM;
#pragma unroll
            for (int nf = 0; nf < 8; nf++) {
                int col = n0 + wn * 64 + nf * 8 + 2 * (l & 3);
                atomicAdd(op + col,     w * c[mf][nf][half_ * 2 + 0]);
                atomicAdd(op + col + 1, w * c[mf][nf][half_ * 2 + 1]);
            }
        }
    }
}

// ---------------- launcher ----------------
extern "C" void kernel_launch(void* const* d_in, const int* in_sizes, int n_in,
                              void* d_out, int out_size) {
    const float* hs = (const float*)d_in[0];
    const float* Wc = (const float*)d_in[1];
    const float* bc = (const float*)d_in[2];
    const float* Wg = (const float*)d_in[3];
    const float* Wu = (const float*)d_in[4];
    const float* Wd = (const float*)d_in[5];
    float* out = (float*)d_out;

    cudaFuncSetAttribute(up_mma_kernel, cudaFuncAttributeMaxDynamicSharedMemorySize, U_SMEM);
    cudaFuncSetAttribute(down_mma_kernel, cudaFuncAttributeMaxDynamicSharedMemorySize, D_SMEM);

    init_kernel<<<1024, 256>>>(out, out_size);
    conv_x_kernel<<<2048, 256>>>(hs);

    __half *wg, *wu, *wd;
    cudaGetSymbolAddress((void**)&wg, g_wg);
    cudaGetSymbolAddress((void**)&wu, g_wu);
    cudaGetSymbolAddress((void**)&wd, g_wd);

    // Wg/Wu: [E][D][I] -> [E][I][D]; Wd: [E][I][D] -> [E][D][I]
    transpose_half_kernel<<<dim3(IDIM / 32, DIM / 64, NE), 256>>>(Wg, wg, DIM, IDIM);
    transpose_half_kernel<<<dim3(IDIM / 32, DIM / 64, NE), 256>>>(Wu, wu, DIM, IDIM);
    transpose_half_kernel<<<dim3(DIM / 32, IDIM / 64, NE), 256>>>(Wd, wd, IDIM, DIM);

    route_kernel<<<(NTOK * 32) / 256, 256>>>(hs, Wc, bc);

    up_mma_kernel<<<dim3(NTOK / 128, IDIM / 64, NE), 256, U_SMEM>>>();
    down_mma_kernel<<<dim3(NTOK / 128, DIM / 128, NE), 256, D_SMEM>>>(out);
}